// round 11
// baseline (speedup 1.0000x reference)
#include <cuda_runtime.h>
#include <cuda_bf16.h>
#include <math.h>

#define BB   256      // batch
#define SSZ  128      // seq len
#define HHD  512      // hidden
#define G4H  2048     // 4*H
#define KIN  414      // F*N
#define KP1  448      // layer-1 K padded to 16
#define KP2  512      // layer-2 K
#define MTOT (SSZ*BB) // 32768

typedef unsigned long long u64;
typedef unsigned int u32;

// ---------------- packed f32x2 helpers (fp32 paths) --------------------------
__device__ __forceinline__ u64 pk2(float lo, float hi) {
    u64 r; asm("mov.b64 %0, {%1, %2};" : "=l"(r) : "f"(lo), "f"(hi)); return r;
}
__device__ __forceinline__ float2 upk2(u64 v) {
    float lo, hi; asm("mov.b64 {%0, %1}, %2;" : "=f"(lo), "=f"(hi) : "l"(v));
    return make_float2(lo, hi);
}
__device__ __forceinline__ u64 ffma2(u64 a, u64 b, u64 c) {
    u64 d; asm("fma.rn.f32x2 %0, %1, %2, %3;" : "=l"(d) : "l"(a), "l"(b), "l"(c));
    return d;
}
#define FMA_TILE(av, bv, acc) do { \
    u64 _b01 = pk2((bv).x, (bv).y), _b23 = pk2((bv).z, (bv).w), _a; \
    _a = pk2((av).x, (av).x); acc[0][0]=ffma2(_a,_b01,acc[0][0]); acc[0][1]=ffma2(_a,_b23,acc[0][1]); \
    _a = pk2((av).y, (av).y); acc[1][0]=ffma2(_a,_b01,acc[1][0]); acc[1][1]=ffma2(_a,_b23,acc[1][1]); \
    _a = pk2((av).z, (av).z); acc[2][0]=ffma2(_a,_b01,acc[2][0]); acc[2][1]=ffma2(_a,_b23,acc[2][1]); \
    _a = pk2((av).w, (av).w); acc[3][0]=ffma2(_a,_b01,acc[3][0]); acc[3][1]=ffma2(_a,_b23,acc[3][1]); \
} while (0)

// ---------------- mma.sync bf16 (HMMA fallback; legal on compute_103) --------
#define MMA_BF16(c, a, b) \
    asm volatile("mma.sync.aligned.m16n8k16.row.col.f32.bf16.bf16.f32 " \
        "{%0,%1,%2,%3}, {%4,%5,%6,%7}, {%8,%9}, {%0,%1,%2,%3};" \
        : "+f"((c)[0]), "+f"((c)[1]), "+f"((c)[2]), "+f"((c)[3]) \
        : "r"((a)[0]), "r"((a)[1]), "r"((a)[2]), "r"((a)[3]), \
          "r"((b)[0]), "r"((b)[1]))

// ---------------- scratch (device globals; no allocations allowed) ----------
__device__ __align__(256) float g_gx[MTOT * G4H];    // [S*B, 2048]
__device__ __align__(256) float g_h1[MTOT * HHD];
__device__ __align__(256) float g_h2[MTOT * HHD];
__device__ __align__(256) __nv_bfloat16 g_xhi[MTOT * KP1];
__device__ __align__(256) __nv_bfloat16 g_xlo[MTOT * KP1];
__device__ __align__(256) __nv_bfloat16 g_hhi[MTOT * KP2];
__device__ __align__(256) __nv_bfloat16 g_hlo[MTOT * KP2];
__device__ __align__(256) __nv_bfloat16 g_w0hi[G4H * KP1];
__device__ __align__(256) __nv_bfloat16 g_w0lo[G4H * KP1];
__device__ __align__(256) __nv_bfloat16 g_w1hi[G4H * KP2];
__device__ __align__(256) __nv_bfloat16 g_w1lo[G4H * KP2];
__device__ unsigned int g_bar;

__global__ void reset_bar_kernel() { g_bar = 0u; }

// ---------------- pack x[B,F,N,S] -> bf16 hi/lo [S*B, 448] -------------------
__global__ void pack_x_kernel(const float* __restrict__ x) {
    __shared__ float tile[32][33];
    int b  = blockIdx.x;
    int k0 = blockIdx.y * 32;
    int s0 = blockIdx.z * 32;
    int tx = threadIdx.x, ty = threadIdx.y;  // 32 x 8
    const float* xb = x + (size_t)b * KIN * SSZ;
#pragma unroll
    for (int i = 0; i < 4; i++) {
        int k = k0 + ty + 8 * i;
        if (k < KIN) tile[ty + 8 * i][tx] = xb[k * SSZ + s0 + tx];
    }
    __syncthreads();
#pragma unroll
    for (int i = 0; i < 4; i++) {
        int s = s0 + ty + 8 * i;
        int k = k0 + tx;
        float v = (k < KIN) ? tile[tx][ty + 8 * i] : 0.f;
        __nv_bfloat16 hi = __float2bfloat16(v);
        float lo = v - __bfloat162float(hi);
        size_t o = (size_t)(s * BB + b) * KP1 + k;
        g_xhi[o] = hi;
        g_xlo[o] = __float2bfloat16(lo);
    }
}

// ---------------- fp32 -> bf16 hi/lo with K pad -------------------------------
__global__ void conv_split_kernel(const float* __restrict__ src, int rows, int Ksrc, int KPd,
                                  __nv_bfloat16* __restrict__ hi, __nv_bfloat16* __restrict__ lo) {
    int idx = blockIdx.x * blockDim.x + threadIdx.x;
    if (idx >= rows * KPd) return;
    int r = idx / KPd, k = idx - r * KPd;
    float v = (k < Ksrc) ? src[(size_t)r * Ksrc + k] : 0.f;
    __nv_bfloat16 h = __float2bfloat16(v);
    hi[idx] = h;
    lo[idx] = __float2bfloat16(v - __bfloat162float(h));
}

// ---------------- HMMA split-bf16 GEMM: C = A.W^T + bias1 + bias2 ------------
// A,B bf16 hi/lo [rows, KPd] K-major. Tile 128(M)x128(N), 8 warps x (64x32).
// Smem tiles 128 rows x 16 bf16, stride 24 bf16 (48B) -> all frag LDS bank-free.
#define TSTR 24

__global__ __launch_bounds__(256) void mma_gemm_kernel(
    const __nv_bfloat16* __restrict__ Ahi, const __nv_bfloat16* __restrict__ Alo,
    const __nv_bfloat16* __restrict__ Bhi, const __nv_bfloat16* __restrict__ Blo,
    int KPd,
    const float* __restrict__ bias1, const float* __restrict__ bias2,
    float* __restrict__ out)
{
    __shared__ __align__(16) __nv_bfloat16 sAh[2][128 * TSTR];
    __shared__ __align__(16) __nv_bfloat16 sAl[2][128 * TSTR];
    __shared__ __align__(16) __nv_bfloat16 sBh[2][128 * TSTR];
    __shared__ __align__(16) __nv_bfloat16 sBl[2][128 * TSTR];
    const int tid  = threadIdx.x;
    const int lane = tid & 31;
    const int wid  = tid >> 5;
    const int g    = lane >> 2, tig = lane & 3;
    const int wm   = wid & 1;          // 2 m-blocks of 64
    const int wn   = wid >> 1;         // 4 n-blocks of 32
    const int n0 = blockIdx.x * 128;
    const int m0 = blockIdx.y * 128;

    // staging: thread -> (row, half-row)
    const int srow = tid >> 1;
    const int sseg = (tid & 1) * 8;
    const __nv_bfloat16* pAh = Ahi + (size_t)(m0 + srow) * KPd + sseg;
    const __nv_bfloat16* pAl = Alo + (size_t)(m0 + srow) * KPd + sseg;
    const __nv_bfloat16* pBh = Bhi + (size_t)(n0 + srow) * KPd + sseg;
    const __nv_bfloat16* pBl = Blo + (size_t)(n0 + srow) * KPd + sseg;
    const int soff = srow * TSTR + sseg;

    float acc[4][4][4];
#pragma unroll
    for (int mi = 0; mi < 4; mi++)
#pragma unroll
        for (int ni = 0; ni < 4; ni++)
#pragma unroll
            for (int q = 0; q < 4; q++) acc[mi][ni][q] = 0.f;

    const int nch = KPd >> 4;

    // stage chunk 0
    *(uint4*)&sAh[0][soff] = *(const uint4*)(pAh);
    *(uint4*)&sAl[0][soff] = *(const uint4*)(pAl);
    *(uint4*)&sBh[0][soff] = *(const uint4*)(pBh);
    *(uint4*)&sBl[0][soff] = *(const uint4*)(pBl);
    __syncthreads();

    for (int kt = 0; kt < nch; kt++) {
        int buf = kt & 1;
        uint4 vah, val, vbh, vbl;
        bool next = (kt + 1 < nch);
        if (next) {
            int ko = (kt + 1) * 16;
            vah = *(const uint4*)(pAh + ko);
            val = *(const uint4*)(pAl + ko);
            vbh = *(const uint4*)(pBh + ko);
            vbl = *(const uint4*)(pBl + ko);
        }

        // load fragments
        u32 ah[4][4], al[4][4], bh[4][2], bl[4][2];
        const __nv_bfloat16* Ah = sAh[buf];
        const __nv_bfloat16* Al = sAl[buf];
        const __nv_bfloat16* Bh = sBh[buf];
        const __nv_bfloat16* Bl = sBl[buf];
        const int ca = 2 * tig;
#pragma unroll
        for (int mi = 0; mi < 4; mi++) {
            int r = wm * 64 + mi * 16 + g;
            ah[mi][0] = *(const u32*)&Ah[r * TSTR + ca];
            ah[mi][1] = *(const u32*)&Ah[(r + 8) * TSTR + ca];
            ah[mi][2] = *(const u32*)&Ah[r * TSTR + ca + 8];
            ah[mi][3] = *(const u32*)&Ah[(r + 8) * TSTR + ca + 8];
            al[mi][0] = *(const u32*)&Al[r * TSTR + ca];
            al[mi][1] = *(const u32*)&Al[(r + 8) * TSTR + ca];
            al[mi][2] = *(const u32*)&Al[r * TSTR + ca + 8];
            al[mi][3] = *(const u32*)&Al[(r + 8) * TSTR + ca + 8];
        }
#pragma unroll
        for (int ni = 0; ni < 4; ni++) {
            int r = wn * 32 + ni * 8 + g;
            bh[ni][0] = *(const u32*)&Bh[r * TSTR + ca];
            bh[ni][1] = *(const u32*)&Bh[r * TSTR + ca + 8];
            bl[ni][0] = *(const u32*)&Bl[r * TSTR + ca];
            bl[ni][1] = *(const u32*)&Bl[r * TSTR + ca + 8];
        }
#pragma unroll
        for (int mi = 0; mi < 4; mi++)
#pragma unroll
            for (int ni = 0; ni < 4; ni++) {
                MMA_BF16(acc[mi][ni], ah[mi], bh[ni]);
                MMA_BF16(acc[mi][ni], ah[mi], bl[ni]);
                MMA_BF16(acc[mi][ni], al[mi], bh[ni]);
            }

        if (next) {
            int nb = buf ^ 1;
            *(uint4*)&sAh[nb][soff] = vah;
            *(uint4*)&sAl[nb][soff] = val;
            *(uint4*)&sBh[nb][soff] = vbh;
            *(uint4*)&sBl[nb][soff] = vbl;
            __syncthreads();
        }
    }

    // epilogue: c0=C[g][2tig], c1=C[g][2tig+1], c2=C[g+8][2tig], c3=C[g+8][2tig+1]
#pragma unroll
    for (int ni = 0; ni < 4; ni++) {
        int j0 = n0 + wn * 32 + ni * 8 + 2 * tig;
        float bs0 = bias1[j0] + bias2[j0];
        float bs1 = bias1[j0 + 1] + bias2[j0 + 1];
#pragma unroll
        for (int mi = 0; mi < 4; mi++) {
            int m = m0 + wm * 64 + mi * 16 + g;
            float2 v0 = make_float2(acc[mi][ni][0] + bs0, acc[mi][ni][1] + bs1);
            float2 v1 = make_float2(acc[mi][ni][2] + bs0, acc[mi][ni][3] + bs1);
            *(float2*)(out + (size_t)m * G4H + j0)       = v0;
            *(float2*)(out + (size_t)(m + 8) * G4H + j0) = v1;
        }
    }
}

// ---------------- persistent LSTM recurrence (R3-proven, unchanged) ----------
#define SMEM_PERSIST ((512 * 68 + 2 * 16 * 68) * (int)sizeof(float))

__global__ __launch_bounds__(256, 1) void lstm_persist_kernel(
    const float* __restrict__ gx,   // [S*B, 2048] (biases folded in)
    const float* __restrict__ whh,  // [2048, 512]
    float* __restrict__ hseq)       // [S*B, 512]
{
    extern __shared__ float sm[];
    float* Ws  = sm;                // [512][68]
    float* Asb = sm + 512 * 68;     // [2][16][68]
    const int tid = threadIdx.x;
    const int bid = blockIdx.x;
    const int m0  = (bid & 3) * 64;
    const int hh0 = (bid >> 2) * 16;
    const int tx = tid & 15, ty = tid >> 4;
    const int lm = tid >> 2, lk = (tid & 3) * 4;

    {
        int c = lm;
        int j = (c & 3) * HHD + hh0 + (c >> 2);
        const float* wr = whh + (size_t)j * HHD;
#pragma unroll 4
        for (int kt = 0; kt < 32; kt++) {
            float4 w4 = *(const float4*)(wr + kt * 16 + lk);
            Ws[(kt * 16 + lk + 0) * 68 + c] = w4.x;
            Ws[(kt * 16 + lk + 1) * 68 + c] = w4.y;
            Ws[(kt * 16 + lk + 2) * 68 + c] = w4.z;
            Ws[(kt * 16 + lk + 3) * 68 + c] = w4.w;
        }
    }
    __syncthreads();

    const int hh = hh0 + tx;
    float creg[4] = {0.f, 0.f, 0.f, 0.f};

    for (int t = 0; t < SSZ; t++) {
        float gxr[4][4];
        const float* gxt = gx + (size_t)t * BB * G4H;
#pragma unroll
        for (int i = 0; i < 4; i++) {
            const float* p = gxt + (size_t)(m0 + ty * 4 + i) * G4H + hh;
            gxr[i][0] = __ldcg(p);
            gxr[i][1] = __ldcg(p + HHD);
            gxr[i][2] = __ldcg(p + 2 * HHD);
            gxr[i][3] = __ldcg(p + 3 * HHD);
        }

        u64 acc[4][2];
#pragma unroll
        for (int i = 0; i < 4; i++) { acc[i][0] = 0ull; acc[i][1] = 0ull; }

        if (t > 0) {
            const float* hprev = hseq + (size_t)(t - 1) * BB * HHD;
            float4 a4 = __ldcg((const float4*)(hprev + (size_t)(m0 + lm) * HHD + lk));
            Asb[(lk + 0) * 68 + lm] = a4.x; Asb[(lk + 1) * 68 + lm] = a4.y;
            Asb[(lk + 2) * 68 + lm] = a4.z; Asb[(lk + 3) * 68 + lm] = a4.w;
            __syncthreads();
            int buf = 0;
            for (int kt = 0; kt < 32; kt++) {
                float4 a4n;
                bool nxt = (kt + 1 < 32);
                if (nxt)
                    a4n = __ldcg((const float4*)(hprev + (size_t)(m0 + lm) * HHD + (kt + 1) * 16 + lk));
                const float* wsb = Ws + (kt * 16) * 68;
#pragma unroll
                for (int k = 0; k < 16; k++) {
                    float4 av = *(const float4*)&Asb[(buf * 16 + k) * 68 + ty * 4];
                    float4 bv = *(const float4*)&wsb[k * 68 + tx * 4];
                    FMA_TILE(av, bv, acc);
                }
                if (nxt) {
                    int nb = buf ^ 1;
                    Asb[(nb * 16 + lk + 0) * 68 + lm] = a4n.x;
                    Asb[(nb * 16 + lk + 1) * 68 + lm] = a4n.y;
                    Asb[(nb * 16 + lk + 2) * 68 + lm] = a4n.z;
                    Asb[(nb * 16 + lk + 3) * 68 + lm] = a4n.w;
                    __syncthreads();
                    buf = nb;
                }
            }
        }

        float* hout = hseq + (size_t)t * BB * HHD;
#pragma unroll
        for (int i = 0; i < 4; i++) {
            float2 p0 = upk2(acc[i][0]);
            float2 p1 = upk2(acc[i][1]);
            float r0 = p0.x + gxr[i][0];
            float r1 = p0.y + gxr[i][1];
            float r2 = p1.x + gxr[i][2];
            float r3 = p1.y + gxr[i][3];
            float ig = 1.f / (1.f + __expf(-r0));
            float fg = 1.f / (1.f + __expf(-r1));
            float gg = tanhf(r2);
            float og = 1.f / (1.f + __expf(-r3));
            float cn = ig * gg + fg * creg[i];
            creg[i] = cn;
            hout[(size_t)(m0 + ty * 4 + i) * HHD + hh] = og * tanhf(cn);
        }

        if (t + 1 < SSZ) {
            __syncthreads();
            if (tid == 0) {
                __threadfence();
                atomicAdd(&g_bar, 1u);
                unsigned tgt = (unsigned)(t + 1) * gridDim.x;
                unsigned v;
                do {
                    asm volatile("ld.global.acquire.gpu.u32 %0, [%1];" : "=r"(v) : "l"(&g_bar));
                } while (v < tgt);
            }
            __syncthreads();
        }
    }
}

// ---------------- FC head (R3-proven): 64x64 tile, transpose store ----------
__global__ __launch_bounds__(256) void fc_kernel(
    const float* __restrict__ A,     // g_h2 [32768, 512]
    const float* __restrict__ W,     // fc_w [414, 512]
    const float* __restrict__ bias,  // fc_b [414]
    float* __restrict__ out)         // [256, 2, 207, 128]
{
    __shared__ __align__(16) float As[2][16][68];
    __shared__ __align__(16) float Bs[2][16][68];
    int m0 = blockIdx.y * 64;
    int n0 = blockIdx.x * 64;
    int tid = threadIdx.x;
    int tx = tid & 15, ty = tid >> 4;
    int lm = tid >> 2;
    int lk = (tid & 3) * 4;
    u64 acc[4][2];
#pragma unroll
    for (int i = 0; i < 4; i++) { acc[i][0] = 0ull; acc[i][1] = 0ull; }
    int jb = n0 + lm;
    bool jv = (jb < KIN);

    {
        float4 a4 = *(const float4*)(A + (size_t)(m0 + lm) * HHD + lk);
        As[0][lk + 0][lm] = a4.x; As[0][lk + 1][lm] = a4.y;
        As[0][lk + 2][lm] = a4.z; As[0][lk + 3][lm] = a4.w;
#pragma unroll
        for (int q = 0; q < 4; q++)
            Bs[0][lk + q][lm] = jv ? W[jb * HHD + lk + q] : 0.f;
    }
    __syncthreads();
    int buf = 0;
    for (int kt = 0; kt < 32; kt++) {
        float4 a4n; float bn[4];
        bool next = (kt + 1 < 32);
        if (next) {
            int kb = (kt + 1) * 16;
            a4n = *(const float4*)(A + (size_t)(m0 + lm) * HHD + kb + lk);
#pragma unroll
            for (int q = 0; q < 4; q++)
                bn[q] = jv ? W[jb * HHD + kb + lk + q] : 0.f;
        }
#pragma unroll
        for (int k = 0; k < 16; k++) {
            float4 av = *(const float4*)&As[buf][k][ty * 4];
            float4 bv = *(const float4*)&Bs[buf][k][tx * 4];
            FMA_TILE(av, bv, acc);
        }
        if (next) {
            int nb = buf ^ 1;
            As[nb][lk + 0][lm] = a4n.x; As[nb][lk + 1][lm] = a4n.y;
            As[nb][lk + 2][lm] = a4n.z; As[nb][lk + 3][lm] = a4n.w;
            Bs[nb][lk + 0][lm] = bn[0]; Bs[nb][lk + 1][lm] = bn[1];
            Bs[nb][lk + 2][lm] = bn[2]; Bs[nb][lk + 3][lm] = bn[3];
            __syncthreads();
            buf = nb;
        }
    }
    float accf[4][4];
#pragma unroll
    for (int i = 0; i < 4; i++) {
        float2 p0 = upk2(acc[i][0]);
        float2 p1 = upk2(acc[i][1]);
        accf[i][0] = p0.x; accf[i][1] = p0.y; accf[i][2] = p1.x; accf[i][3] = p1.y;
    }
#pragma unroll
    for (int i = 0; i < 4; i++) {
        int m = m0 + ty * 4 + i;
        int s = m >> 8;
        int b = m & 255;
#pragma unroll
        for (int jj = 0; jj < 4; jj++) {
            int j = n0 + tx * 4 + jj;
            if (j < KIN) {
                int oc = j / 207;
                int n  = j - oc * 207;
                out[(size_t)((b * 2 + oc) * 207 + n) * SSZ + s] = accf[i][jj] + bias[j];
            }
        }
    }
}

// ---------------- launch -----------------------------------------------------
extern "C" void kernel_launch(void* const* d_in, const int* in_sizes, int n_in,
                              void* d_out, int out_size)
{
    const float* x     = (const float*)d_in[0];
    const float* w_ih0 = (const float*)d_in[1];
    const float* w_hh0 = (const float*)d_in[2];
    const float* b_ih0 = (const float*)d_in[3];
    const float* b_hh0 = (const float*)d_in[4];
    const float* w_ih1 = (const float*)d_in[5];
    const float* w_hh1 = (const float*)d_in[6];
    const float* b_ih1 = (const float*)d_in[7];
    const float* b_hh1 = (const float*)d_in[8];
    const float* fc_w  = (const float*)d_in[9];
    const float* fc_b  = (const float*)d_in[10];
    float* out = (float*)d_out;

    float *gx, *h1, *h2;
    __nv_bfloat16 *xhi, *xlo, *hhi, *hlo, *w0hi, *w0lo, *w1hi, *w1lo;
    cudaGetSymbolAddress((void**)&gx,  g_gx);
    cudaGetSymbolAddress((void**)&h1,  g_h1);
    cudaGetSymbolAddress((void**)&h2,  g_h2);
    cudaGetSymbolAddress((void**)&xhi, g_xhi);
    cudaGetSymbolAddress((void**)&xlo, g_xlo);
    cudaGetSymbolAddress((void**)&hhi, g_hhi);
    cudaGetSymbolAddress((void**)&hlo, g_hlo);
    cudaGetSymbolAddress((void**)&w0hi, g_w0hi);
    cudaGetSymbolAddress((void**)&w0lo, g_w0lo);
    cudaGetSymbolAddress((void**)&w1hi, g_w1hi);
    cudaGetSymbolAddress((void**)&w1lo, g_w1lo);

    cudaFuncSetAttribute(lstm_persist_kernel,
                         cudaFuncAttributeMaxDynamicSharedMemorySize, SMEM_PERSIST);

    // 1) pack x -> bf16 hi/lo [S*B, 448]
    pack_x_kernel<<<dim3(256, 14, 4), dim3(32, 8)>>>(x);

    // 2) weight splits
    conv_split_kernel<<<(G4H * KP1 + 255) / 256, 256>>>(w_ih0, G4H, KIN, KP1, w0hi, w0lo);
    conv_split_kernel<<<(G4H * KP2 + 255) / 256, 256>>>(w_ih1, G4H, HHD, KP2, w1hi, w1lo);

    // 3) gx = xs @ w_ih0^T + b_ih0 + b_hh0  (HMMA split-bf16)
    mma_gemm_kernel<<<dim3(G4H / 128, MTOT / 128), 256>>>(
        xhi, xlo, w0hi, w0lo, KP1, b_ih0, b_hh0, gx);

    // 4) layer 1 recurrence
    reset_bar_kernel<<<1, 1>>>();
    lstm_persist_kernel<<<128, 256, SMEM_PERSIST>>>(gx, w_hh0, h1);

    // 5) h1 -> bf16 hi/lo, then gx = h1 @ w_ih1^T + b_ih1 + b_hh1
    conv_split_kernel<<<(MTOT * KP2 + 255) / 256, 256>>>(h1, MTOT, HHD, KP2, hhi, hlo);
    mma_gemm_kernel<<<dim3(G4H / 128, MTOT / 128), 256>>>(
        hhi, hlo, w1hi, w1lo, KP2, b_ih1, b_hh1, gx);

    // 6) layer 2 recurrence
    reset_bar_kernel<<<1, 1>>>();
    lstm_persist_kernel<<<128, 256, SMEM_PERSIST>>>(gx, w_hh1, h2);

    // 7) FC head + output transpose (fp32)
    fc_kernel<<<dim3(7, MTOT / 64), 256>>>(h2, fc_w, fc_b, out);
}

// round 12
// speedup vs baseline: 1.0021x; 1.0021x over previous
#include <cuda_runtime.h>
#include <cuda_bf16.h>
#include <math.h>

#define BB   256      // batch
#define SSZ  128      // seq len
#define HHD  512      // hidden
#define G4H  2048     // 4*H
#define KIN  414      // F*N
#define KP1  448      // layer-1 K padded to 16
#define KP2  512      // layer-2 K
#define MTOT (SSZ*BB) // 32768

typedef unsigned long long u64;
typedef unsigned int u32;

// ---------------- packed f32x2 helpers (fp32 paths) --------------------------
__device__ __forceinline__ u64 pk2(float lo, float hi) {
    u64 r; asm("mov.b64 %0, {%1, %2};" : "=l"(r) : "f"(lo), "f"(hi)); return r;
}
__device__ __forceinline__ float2 upk2(u64 v) {
    float lo, hi; asm("mov.b64 {%0, %1}, %2;" : "=f"(lo), "=f"(hi) : "l"(v));
    return make_float2(lo, hi);
}
__device__ __forceinline__ u64 ffma2(u64 a, u64 b, u64 c) {
    u64 d; asm("fma.rn.f32x2 %0, %1, %2, %3;" : "=l"(d) : "l"(a), "l"(b), "l"(c));
    return d;
}
#define FMA_TILE(av, bv, acc) do { \
    u64 _b01 = pk2((bv).x, (bv).y), _b23 = pk2((bv).z, (bv).w), _a; \
    _a = pk2((av).x, (av).x); acc[0][0]=ffma2(_a,_b01,acc[0][0]); acc[0][1]=ffma2(_a,_b23,acc[0][1]); \
    _a = pk2((av).y, (av).y); acc[1][0]=ffma2(_a,_b01,acc[1][0]); acc[1][1]=ffma2(_a,_b23,acc[1][1]); \
    _a = pk2((av).z, (av).z); acc[2][0]=ffma2(_a,_b01,acc[2][0]); acc[2][1]=ffma2(_a,_b23,acc[2][1]); \
    _a = pk2((av).w, (av).w); acc[3][0]=ffma2(_a,_b01,acc[3][0]); acc[3][1]=ffma2(_a,_b23,acc[3][1]); \
} while (0)

// ---------------- mma.sync bf16 (HMMA fallback; legal on compute_103) --------
#define MMA_BF16(c, a, b) \
    asm volatile("mma.sync.aligned.m16n8k16.row.col.f32.bf16.bf16.f32 " \
        "{%0,%1,%2,%3}, {%4,%5,%6,%7}, {%8,%9}, {%0,%1,%2,%3};" \
        : "+f"((c)[0]), "+f"((c)[1]), "+f"((c)[2]), "+f"((c)[3]) \
        : "r"((a)[0]), "r"((a)[1]), "r"((a)[2]), "r"((a)[3]), \
          "r"((b)[0]), "r"((b)[1]))

// ---------------- scratch (device globals; no allocations allowed) ----------
__device__ __align__(256) float g_gx[MTOT * G4H];    // [S*B, 2048]
__device__ __align__(256) float g_h1[MTOT * HHD];
__device__ __align__(256) float g_h2[MTOT * HHD];
__device__ __align__(256) __nv_bfloat16 g_xhi[MTOT * KP1];
__device__ __align__(256) __nv_bfloat16 g_xlo[MTOT * KP1];
__device__ __align__(256) __nv_bfloat16 g_hhi[MTOT * KP2];
__device__ __align__(256) __nv_bfloat16 g_hlo[MTOT * KP2];
__device__ __align__(256) __nv_bfloat16 g_w0hi[G4H * KP1];
__device__ __align__(256) __nv_bfloat16 g_w0lo[G4H * KP1];
__device__ __align__(256) __nv_bfloat16 g_w1hi[G4H * KP2];
__device__ __align__(256) __nv_bfloat16 g_w1lo[G4H * KP2];
__device__ unsigned int g_bar;

__global__ void reset_bar_kernel() { g_bar = 0u; }

// ---------------- pack x[B,F,N,S] -> bf16 hi/lo [S*B, 448] -------------------
__global__ void pack_x_kernel(const float* __restrict__ x) {
    __shared__ float tile[32][33];
    int b  = blockIdx.x;
    int k0 = blockIdx.y * 32;
    int s0 = blockIdx.z * 32;
    int tx = threadIdx.x, ty = threadIdx.y;  // 32 x 8
    const float* xb = x + (size_t)b * KIN * SSZ;
#pragma unroll
    for (int i = 0; i < 4; i++) {
        int k = k0 + ty + 8 * i;
        if (k < KIN) tile[ty + 8 * i][tx] = xb[k * SSZ + s0 + tx];
    }
    __syncthreads();
#pragma unroll
    for (int i = 0; i < 4; i++) {
        int s = s0 + ty + 8 * i;
        int k = k0 + tx;
        float v = (k < KIN) ? tile[tx][ty + 8 * i] : 0.f;
        __nv_bfloat16 hi = __float2bfloat16(v);
        float lo = v - __bfloat162float(hi);
        size_t o = (size_t)(s * BB + b) * KP1 + k;
        g_xhi[o] = hi;
        g_xlo[o] = __float2bfloat16(lo);
    }
}

// ---------------- fp32 -> bf16 hi/lo with K pad -------------------------------
__global__ void conv_split_kernel(const float* __restrict__ src, int rows, int Ksrc, int KPd,
                                  __nv_bfloat16* __restrict__ hi, __nv_bfloat16* __restrict__ lo) {
    int idx = blockIdx.x * blockDim.x + threadIdx.x;
    if (idx >= rows * KPd) return;
    int r = idx / KPd, k = idx - r * KPd;
    float v = (k < Ksrc) ? src[(size_t)r * Ksrc + k] : 0.f;
    __nv_bfloat16 h = __float2bfloat16(v);
    hi[idx] = h;
    lo[idx] = __float2bfloat16(v - __bfloat162float(h));
}

// ---------------- HMMA split-bf16 GEMM: C = A.W^T + bias1 + bias2 ------------
// A,B bf16 hi/lo [rows, KPd] K-major. Tile 128(M)x128(N), 8 warps x (64x32).
// Smem tiles 128 rows x 16 bf16, stride 24 bf16 (48B) -> all frag LDS bank-free.
#define TSTR 24

__global__ __launch_bounds__(256) void mma_gemm_kernel(
    const __nv_bfloat16* __restrict__ Ahi, const __nv_bfloat16* __restrict__ Alo,
    const __nv_bfloat16* __restrict__ Bhi, const __nv_bfloat16* __restrict__ Blo,
    int KPd,
    const float* __restrict__ bias1, const float* __restrict__ bias2,
    float* __restrict__ out)
{
    __shared__ __align__(16) __nv_bfloat16 sAh[2][128 * TSTR];
    __shared__ __align__(16) __nv_bfloat16 sAl[2][128 * TSTR];
    __shared__ __align__(16) __nv_bfloat16 sBh[2][128 * TSTR];
    __shared__ __align__(16) __nv_bfloat16 sBl[2][128 * TSTR];
    const int tid  = threadIdx.x;
    const int lane = tid & 31;
    const int wid  = tid >> 5;
    const int g    = lane >> 2, tig = lane & 3;
    const int wm   = wid & 1;          // 2 m-blocks of 64
    const int wn   = wid >> 1;         // 4 n-blocks of 32
    const int n0 = blockIdx.x * 128;
    const int m0 = blockIdx.y * 128;

    // staging: thread -> (row, half-row)
    const int srow = tid >> 1;
    const int sseg = (tid & 1) * 8;
    const __nv_bfloat16* pAh = Ahi + (size_t)(m0 + srow) * KPd + sseg;
    const __nv_bfloat16* pAl = Alo + (size_t)(m0 + srow) * KPd + sseg;
    const __nv_bfloat16* pBh = Bhi + (size_t)(n0 + srow) * KPd + sseg;
    const __nv_bfloat16* pBl = Blo + (size_t)(n0 + srow) * KPd + sseg;
    const int soff = srow * TSTR + sseg;

    float acc[4][4][4];
#pragma unroll
    for (int mi = 0; mi < 4; mi++)
#pragma unroll
        for (int ni = 0; ni < 4; ni++)
#pragma unroll
            for (int q = 0; q < 4; q++) acc[mi][ni][q] = 0.f;

    const int nch = KPd >> 4;

    // stage chunk 0
    *(uint4*)&sAh[0][soff] = *(const uint4*)(pAh);
    *(uint4*)&sAl[0][soff] = *(const uint4*)(pAl);
    *(uint4*)&sBh[0][soff] = *(const uint4*)(pBh);
    *(uint4*)&sBl[0][soff] = *(const uint4*)(pBl);
    __syncthreads();

    for (int kt = 0; kt < nch; kt++) {
        int buf = kt & 1;
        uint4 vah, val, vbh, vbl;
        bool next = (kt + 1 < nch);
        if (next) {
            int ko = (kt + 1) * 16;
            vah = *(const uint4*)(pAh + ko);
            val = *(const uint4*)(pAl + ko);
            vbh = *(const uint4*)(pBh + ko);
            vbl = *(const uint4*)(pBl + ko);
        }

        // load fragments
        u32 ah[4][4], al[4][4], bh[4][2], bl[4][2];
        const __nv_bfloat16* Ah = sAh[buf];
        const __nv_bfloat16* Al = sAl[buf];
        const __nv_bfloat16* Bh = sBh[buf];
        const __nv_bfloat16* Bl = sBl[buf];
        const int ca = 2 * tig;
#pragma unroll
        for (int mi = 0; mi < 4; mi++) {
            int r = wm * 64 + mi * 16 + g;
            ah[mi][0] = *(const u32*)&Ah[r * TSTR + ca];
            ah[mi][1] = *(const u32*)&Ah[(r + 8) * TSTR + ca];
            ah[mi][2] = *(const u32*)&Ah[r * TSTR + ca + 8];
            ah[mi][3] = *(const u32*)&Ah[(r + 8) * TSTR + ca + 8];
            al[mi][0] = *(const u32*)&Al[r * TSTR + ca];
            al[mi][1] = *(const u32*)&Al[(r + 8) * TSTR + ca];
            al[mi][2] = *(const u32*)&Al[r * TSTR + ca + 8];
            al[mi][3] = *(const u32*)&Al[(r + 8) * TSTR + ca + 8];
        }
#pragma unroll
        for (int ni = 0; ni < 4; ni++) {
            int r = wn * 32 + ni * 8 + g;
            bh[ni][0] = *(const u32*)&Bh[r * TSTR + ca];
            bh[ni][1] = *(const u32*)&Bh[r * TSTR + ca + 8];
            bl[ni][0] = *(const u32*)&Bl[r * TSTR + ca];
            bl[ni][1] = *(const u32*)&Bl[r * TSTR + ca + 8];
        }
#pragma unroll
        for (int mi = 0; mi < 4; mi++)
#pragma unroll
            for (int ni = 0; ni < 4; ni++) {
                MMA_BF16(acc[mi][ni], ah[mi], bh[ni]);
                MMA_BF16(acc[mi][ni], ah[mi], bl[ni]);
                MMA_BF16(acc[mi][ni], al[mi], bh[ni]);
            }

        if (next) {
            int nb = buf ^ 1;
            *(uint4*)&sAh[nb][soff] = vah;
            *(uint4*)&sAl[nb][soff] = val;
            *(uint4*)&sBh[nb][soff] = vbh;
            *(uint4*)&sBl[nb][soff] = vbl;
            __syncthreads();
        }
    }

    // epilogue: c0=C[g][2tig], c1=C[g][2tig+1], c2=C[g+8][2tig], c3=C[g+8][2tig+1]
#pragma unroll
    for (int ni = 0; ni < 4; ni++) {
        int j0 = n0 + wn * 32 + ni * 8 + 2 * tig;
        float bs0 = bias1[j0] + bias2[j0];
        float bs1 = bias1[j0 + 1] + bias2[j0 + 1];
#pragma unroll
        for (int mi = 0; mi < 4; mi++) {
            int m = m0 + wm * 64 + mi * 16 + g;
            float2 v0 = make_float2(acc[mi][ni][0] + bs0, acc[mi][ni][1] + bs1);
            float2 v1 = make_float2(acc[mi][ni][2] + bs0, acc[mi][ni][3] + bs1);
            *(float2*)(out + (size_t)m * G4H + j0)       = v0;
            *(float2*)(out + (size_t)(m + 8) * G4H + j0) = v1;
        }
    }
}

// ---------------- persistent LSTM recurrence (R3-proven, unchanged) ----------
#define SMEM_PERSIST ((512 * 68 + 2 * 16 * 68) * (int)sizeof(float))

__global__ __launch_bounds__(256, 1) void lstm_persist_kernel(
    const float* __restrict__ gx,   // [S*B, 2048] (biases folded in)
    const float* __restrict__ whh,  // [2048, 512]
    float* __restrict__ hseq)       // [S*B, 512]
{
    extern __shared__ float sm[];
    float* Ws  = sm;                // [512][68]
    float* Asb = sm + 512 * 68;     // [2][16][68]
    const int tid = threadIdx.x;
    const int bid = blockIdx.x;
    const int m0  = (bid & 3) * 64;
    const int hh0 = (bid >> 2) * 16;
    const int tx = tid & 15, ty = tid >> 4;
    const int lm = tid >> 2, lk = (tid & 3) * 4;

    {
        int c = lm;
        int j = (c & 3) * HHD + hh0 + (c >> 2);
        const float* wr = whh + (size_t)j * HHD;
#pragma unroll 4
        for (int kt = 0; kt < 32; kt++) {
            float4 w4 = *(const float4*)(wr + kt * 16 + lk);
            Ws[(kt * 16 + lk + 0) * 68 + c] = w4.x;
            Ws[(kt * 16 + lk + 1) * 68 + c] = w4.y;
            Ws[(kt * 16 + lk + 2) * 68 + c] = w4.z;
            Ws[(kt * 16 + lk + 3) * 68 + c] = w4.w;
        }
    }
    __syncthreads();

    const int hh = hh0 + tx;
    float creg[4] = {0.f, 0.f, 0.f, 0.f};

    for (int t = 0; t < SSZ; t++) {
        float gxr[4][4];
        const float* gxt = gx + (size_t)t * BB * G4H;
#pragma unroll
        for (int i = 0; i < 4; i++) {
            const float* p = gxt + (size_t)(m0 + ty * 4 + i) * G4H + hh;
            gxr[i][0] = __ldcg(p);
            gxr[i][1] = __ldcg(p + HHD);
            gxr[i][2] = __ldcg(p + 2 * HHD);
            gxr[i][3] = __ldcg(p + 3 * HHD);
        }

        u64 acc[4][2];
#pragma unroll
        for (int i = 0; i < 4; i++) { acc[i][0] = 0ull; acc[i][1] = 0ull; }

        if (t > 0) {
            const float* hprev = hseq + (size_t)(t - 1) * BB * HHD;
            float4 a4 = __ldcg((const float4*)(hprev + (size_t)(m0 + lm) * HHD + lk));
            Asb[(lk + 0) * 68 + lm] = a4.x; Asb[(lk + 1) * 68 + lm] = a4.y;
            Asb[(lk + 2) * 68 + lm] = a4.z; Asb[(lk + 3) * 68 + lm] = a4.w;
            __syncthreads();
            int buf = 0;
            for (int kt = 0; kt < 32; kt++) {
                float4 a4n;
                bool nxt = (kt + 1 < 32);
                if (nxt)
                    a4n = __ldcg((const float4*)(hprev + (size_t)(m0 + lm) * HHD + (kt + 1) * 16 + lk));
                const float* wsb = Ws + (kt * 16) * 68;
#pragma unroll
                for (int k = 0; k < 16; k++) {
                    float4 av = *(const float4*)&Asb[(buf * 16 + k) * 68 + ty * 4];
                    float4 bv = *(const float4*)&wsb[k * 68 + tx * 4];
                    FMA_TILE(av, bv, acc);
                }
                if (nxt) {
                    int nb = buf ^ 1;
                    Asb[(nb * 16 + lk + 0) * 68 + lm] = a4n.x;
                    Asb[(nb * 16 + lk + 1) * 68 + lm] = a4n.y;
                    Asb[(nb * 16 + lk + 2) * 68 + lm] = a4n.z;
                    Asb[(nb * 16 + lk + 3) * 68 + lm] = a4n.w;
                    __syncthreads();
                    buf = nb;
                }
            }
        }

        float* hout = hseq + (size_t)t * BB * HHD;
#pragma unroll
        for (int i = 0; i < 4; i++) {
            float2 p0 = upk2(acc[i][0]);
            float2 p1 = upk2(acc[i][1]);
            float r0 = p0.x + gxr[i][0];
            float r1 = p0.y + gxr[i][1];
            float r2 = p1.x + gxr[i][2];
            float r3 = p1.y + gxr[i][3];
            float ig = 1.f / (1.f + __expf(-r0));
            float fg = 1.f / (1.f + __expf(-r1));
            float gg = tanhf(r2);
            float og = 1.f / (1.f + __expf(-r3));
            float cn = ig * gg + fg * creg[i];
            creg[i] = cn;
            hout[(size_t)(m0 + ty * 4 + i) * HHD + hh] = og * tanhf(cn);
        }

        if (t + 1 < SSZ) {
            __syncthreads();
            if (tid == 0) {
                __threadfence();
                atomicAdd(&g_bar, 1u);
                unsigned tgt = (unsigned)(t + 1) * gridDim.x;
                unsigned v;
                do {
                    asm volatile("ld.global.acquire.gpu.u32 %0, [%1];" : "=r"(v) : "l"(&g_bar));
                } while (v < tgt);
            }
            __syncthreads();
        }
    }
}

// ---------------- FC head (R3-proven): 64x64 tile, transpose store ----------
__global__ __launch_bounds__(256) void fc_kernel(
    const float* __restrict__ A,     // g_h2 [32768, 512]
    const float* __restrict__ W,     // fc_w [414, 512]
    const float* __restrict__ bias,  // fc_b [414]
    float* __restrict__ out)         // [256, 2, 207, 128]
{
    __shared__ __align__(16) float As[2][16][68];
    __shared__ __align__(16) float Bs[2][16][68];
    int m0 = blockIdx.y * 64;
    int n0 = blockIdx.x * 64;
    int tid = threadIdx.x;
    int tx = tid & 15, ty = tid >> 4;
    int lm = tid >> 2;
    int lk = (tid & 3) * 4;
    u64 acc[4][2];
#pragma unroll
    for (int i = 0; i < 4; i++) { acc[i][0] = 0ull; acc[i][1] = 0ull; }
    int jb = n0 + lm;
    bool jv = (jb < KIN);

    {
        float4 a4 = *(const float4*)(A + (size_t)(m0 + lm) * HHD + lk);
        As[0][lk + 0][lm] = a4.x; As[0][lk + 1][lm] = a4.y;
        As[0][lk + 2][lm] = a4.z; As[0][lk + 3][lm] = a4.w;
#pragma unroll
        for (int q = 0; q < 4; q++)
            Bs[0][lk + q][lm] = jv ? W[jb * HHD + lk + q] : 0.f;
    }
    __syncthreads();
    int buf = 0;
    for (int kt = 0; kt < 32; kt++) {
        float4 a4n; float bn[4];
        bool next = (kt + 1 < 32);
        if (next) {
            int kb = (kt + 1) * 16;
            a4n = *(const float4*)(A + (size_t)(m0 + lm) * HHD + kb + lk);
#pragma unroll
            for (int q = 0; q < 4; q++)
                bn[q] = jv ? W[jb * HHD + kb + lk + q] : 0.f;
        }
#pragma unroll
        for (int k = 0; k < 16; k++) {
            float4 av = *(const float4*)&As[buf][k][ty * 4];
            float4 bv = *(const float4*)&Bs[buf][k][tx * 4];
            FMA_TILE(av, bv, acc);
        }
        if (next) {
            int nb = buf ^ 1;
            As[nb][lk + 0][lm] = a4n.x; As[nb][lk + 1][lm] = a4n.y;
            As[nb][lk + 2][lm] = a4n.z; As[nb][lk + 3][lm] = a4n.w;
            Bs[nb][lk + 0][lm] = bn[0]; Bs[nb][lk + 1][lm] = bn[1];
            Bs[nb][lk + 2][lm] = bn[2]; Bs[nb][lk + 3][lm] = bn[3];
            __syncthreads();
            buf = nb;
        }
    }
    float accf[4][4];
#pragma unroll
    for (int i = 0; i < 4; i++) {
        float2 p0 = upk2(acc[i][0]);
        float2 p1 = upk2(acc[i][1]);
        accf[i][0] = p0.x; accf[i][1] = p0.y; accf[i][2] = p1.x; accf[i][3] = p1.y;
    }
#pragma unroll
    for (int i = 0; i < 4; i++) {
        int m = m0 + ty * 4 + i;
        int s = m >> 8;
        int b = m & 255;
#pragma unroll
        for (int jj = 0; jj < 4; jj++) {
            int j = n0 + tx * 4 + jj;
            if (j < KIN) {
                int oc = j / 207;
                int n  = j - oc * 207;
                out[(size_t)((b * 2 + oc) * 207 + n) * SSZ + s] = accf[i][jj] + bias[j];
            }
        }
    }
}

// ---------------- launch -----------------------------------------------------
extern "C" void kernel_launch(void* const* d_in, const int* in_sizes, int n_in,
                              void* d_out, int out_size)
{
    const float* x     = (const float*)d_in[0];
    const float* w_ih0 = (const float*)d_in[1];
    const float* w_hh0 = (const float*)d_in[2];
    const float* b_ih0 = (const float*)d_in[3];
    const float* b_hh0 = (const float*)d_in[4];
    const float* w_ih1 = (const float*)d_in[5];
    const float* w_hh1 = (const float*)d_in[6];
    const float* b_ih1 = (const float*)d_in[7];
    const float* b_hh1 = (const float*)d_in[8];
    const float* fc_w  = (const float*)d_in[9];
    const float* fc_b  = (const float*)d_in[10];
    float* out = (float*)d_out;

    float *gx, *h1, *h2;
    __nv_bfloat16 *xhi, *xlo, *hhi, *hlo, *w0hi, *w0lo, *w1hi, *w1lo;
    cudaGetSymbolAddress((void**)&gx,  g_gx);
    cudaGetSymbolAddress((void**)&h1,  g_h1);
    cudaGetSymbolAddress((void**)&h2,  g_h2);
    cudaGetSymbolAddress((void**)&xhi, g_xhi);
    cudaGetSymbolAddress((void**)&xlo, g_xlo);
    cudaGetSymbolAddress((void**)&hhi, g_hhi);
    cudaGetSymbolAddress((void**)&hlo, g_hlo);
    cudaGetSymbolAddress((void**)&w0hi, g_w0hi);
    cudaGetSymbolAddress((void**)&w0lo, g_w0lo);
    cudaGetSymbolAddress((void**)&w1hi, g_w1hi);
    cudaGetSymbolAddress((void**)&w1lo, g_w1lo);

    cudaFuncSetAttribute(lstm_persist_kernel,
                         cudaFuncAttributeMaxDynamicSharedMemorySize, SMEM_PERSIST);

    // 1) pack x -> bf16 hi/lo [S*B, 448]
    pack_x_kernel<<<dim3(256, 14, 4), dim3(32, 8)>>>(x);

    // 2) weight splits
    conv_split_kernel<<<(G4H * KP1 + 255) / 256, 256>>>(w_ih0, G4H, KIN, KP1, w0hi, w0lo);
    conv_split_kernel<<<(G4H * KP2 + 255) / 256, 256>>>(w_ih1, G4H, HHD, KP2, w1hi, w1lo);

    // 3) gx = xs @ w_ih0^T + b_ih0 + b_hh0  (HMMA split-bf16)
    mma_gemm_kernel<<<dim3(G4H / 128, MTOT / 128), 256>>>(
        xhi, xlo, w0hi, w0lo, KP1, b_ih0, b_hh0, gx);

    // 4) layer 1 recurrence
    reset_bar_kernel<<<1, 1>>>();
    lstm_persist_kernel<<<128, 256, SMEM_PERSIST>>>(gx, w_hh0, h1);

    // 5) h1 -> bf16 hi/lo, then gx = h1 @ w_ih1^T + b_ih1 + b_hh1
    conv_split_kernel<<<(MTOT * KP2 + 255) / 256, 256>>>(h1, MTOT, HHD, KP2, hhi, hlo);
    mma_gemm_kernel<<<dim3(G4H / 128, MTOT / 128), 256>>>(
        hhi, hlo, w1hi, w1lo, KP2, b_ih1, b_hh1, gx);

    // 6) layer 2 recurrence
    reset_bar_kernel<<<1, 1>>>();
    lstm_persist_kernel<<<128, 256, SMEM_PERSIST>>>(gx, w_hh1, h2);

    // 7) FC head + output transpose (fp32)
    fc_kernel<<<dim3(7, MTOT / 64), 256>>>(h2, fc_w, fc_b, out);
}

// round 14
// speedup vs baseline: 1.2516x; 1.2490x over previous
#include <cuda_runtime.h>
#include <cuda_bf16.h>
#include <math.h>

#define BB   256      // batch
#define SSZ  128      // seq len
#define HHD  512      // hidden
#define G4H  2048     // 4*H
#define KIN  414      // F*N
#define KP1  448      // layer-1 K padded to 16
#define KP2  512      // layer-2 K
#define MTOT (SSZ*BB) // 32768

typedef unsigned long long u64;
typedef unsigned int u32;

// ---------------- packed f32x2 helpers (fp32 paths) --------------------------
__device__ __forceinline__ u64 pk2(float lo, float hi) {
    u64 r; asm("mov.b64 %0, {%1, %2};" : "=l"(r) : "f"(lo), "f"(hi)); return r;
}
__device__ __forceinline__ float2 upk2(u64 v) {
    float lo, hi; asm("mov.b64 {%0, %1}, %2;" : "=f"(lo), "=f"(hi) : "l"(v));
    return make_float2(lo, hi);
}
__device__ __forceinline__ u64 ffma2(u64 a, u64 b, u64 c) {
    u64 d; asm("fma.rn.f32x2 %0, %1, %2, %3;" : "=l"(d) : "l"(a), "l"(b), "l"(c));
    return d;
}
#define FMA_TILE(av, bv, acc) do { \
    u64 _b01 = pk2((bv).x, (bv).y), _b23 = pk2((bv).z, (bv).w), _a; \
    _a = pk2((av).x, (av).x); acc[0][0]=ffma2(_a,_b01,acc[0][0]); acc[0][1]=ffma2(_a,_b23,acc[0][1]); \
    _a = pk2((av).y, (av).y); acc[1][0]=ffma2(_a,_b01,acc[1][0]); acc[1][1]=ffma2(_a,_b23,acc[1][1]); \
    _a = pk2((av).z, (av).z); acc[2][0]=ffma2(_a,_b01,acc[2][0]); acc[2][1]=ffma2(_a,_b23,acc[2][1]); \
    _a = pk2((av).w, (av).w); acc[3][0]=ffma2(_a,_b01,acc[3][0]); acc[3][1]=ffma2(_a,_b23,acc[3][1]); \
} while (0)

// ---------------- mma.sync bf16 (HMMA fallback; legal on compute_103) --------
#define MMA_BF16(c, a, b) \
    asm volatile("mma.sync.aligned.m16n8k16.row.col.f32.bf16.bf16.f32 " \
        "{%0,%1,%2,%3}, {%4,%5,%6,%7}, {%8,%9}, {%0,%1,%2,%3};" \
        : "+f"((c)[0]), "+f"((c)[1]), "+f"((c)[2]), "+f"((c)[3]) \
        : "r"((a)[0]), "r"((a)[1]), "r"((a)[2]), "r"((a)[3]), \
          "r"((b)[0]), "r"((b)[1]))

// ---------------- scratch (device globals; no allocations allowed) ----------
__device__ __align__(256) float g_gx[MTOT * G4H];    // [S*B, 2048]
__device__ __align__(256) float g_h2[MTOT * HHD];    // fp32 h2 (FC input)
__device__ __align__(256) __nv_bfloat16 g_xhi[MTOT * KP1];
__device__ __align__(256) __nv_bfloat16 g_xlo[MTOT * KP1];
__device__ __align__(256) __nv_bfloat16 g_h1hi[MTOT * KP2];
__device__ __align__(256) __nv_bfloat16 g_h1lo[MTOT * KP2];
__device__ __align__(256) __nv_bfloat16 g_h2hi[MTOT * KP2];
__device__ __align__(256) __nv_bfloat16 g_h2lo[MTOT * KP2];
__device__ __align__(256) __nv_bfloat16 g_w0hi[G4H * KP1];
__device__ __align__(256) __nv_bfloat16 g_w0lo[G4H * KP1];
__device__ __align__(256) __nv_bfloat16 g_w1hi[G4H * KP2];
__device__ __align__(256) __nv_bfloat16 g_w1lo[G4H * KP2];
__device__ __align__(256) __nv_bfloat16 g_wh0hi[G4H * HHD];
__device__ __align__(256) __nv_bfloat16 g_wh0lo[G4H * HHD];
__device__ __align__(256) __nv_bfloat16 g_wh1hi[G4H * HHD];
__device__ __align__(256) __nv_bfloat16 g_wh1lo[G4H * HHD];
__device__ unsigned int g_bar;

__global__ void reset_bar_kernel() { g_bar = 0u; }

// ---------------- pack x[B,F,N,S] -> bf16 hi/lo [S*B, 448] -------------------
__global__ void pack_x_kernel(const float* __restrict__ x) {
    __shared__ float tile[32][33];
    int b  = blockIdx.x;
    int k0 = blockIdx.y * 32;
    int s0 = blockIdx.z * 32;
    int tx = threadIdx.x, ty = threadIdx.y;  // 32 x 8
    const float* xb = x + (size_t)b * KIN * SSZ;
#pragma unroll
    for (int i = 0; i < 4; i++) {
        int k = k0 + ty + 8 * i;
        if (k < KIN) tile[ty + 8 * i][tx] = xb[k * SSZ + s0 + tx];
    }
    __syncthreads();
#pragma unroll
    for (int i = 0; i < 4; i++) {
        int s = s0 + ty + 8 * i;
        int k = k0 + tx;
        float v = (k < KIN) ? tile[tx][ty + 8 * i] : 0.f;
        __nv_bfloat16 hi = __float2bfloat16(v);
        float lo = v - __bfloat162float(hi);
        size_t o = (size_t)(s * BB + b) * KP1 + k;
        g_xhi[o] = hi;
        g_xlo[o] = __float2bfloat16(lo);
    }
}

// ---------------- fp32 -> bf16 hi/lo with K pad -------------------------------
__global__ void conv_split_kernel(const float* __restrict__ src, int rows, int Ksrc, int KPd,
                                  __nv_bfloat16* __restrict__ hi, __nv_bfloat16* __restrict__ lo) {
    int idx = blockIdx.x * blockDim.x + threadIdx.x;
    if (idx >= rows * KPd) return;
    int r = idx / KPd, k = idx - r * KPd;
    float v = (k < Ksrc) ? src[(size_t)r * Ksrc + k] : 0.f;
    __nv_bfloat16 h = __float2bfloat16(v);
    hi[idx] = h;
    lo[idx] = __float2bfloat16(v - __bfloat162float(h));
}

// ---------------- HMMA split-bf16 GEMM (R12-proven) --------------------------
#define TSTR 24

__global__ __launch_bounds__(256) void mma_gemm_kernel(
    const __nv_bfloat16* __restrict__ Ahi, const __nv_bfloat16* __restrict__ Alo,
    const __nv_bfloat16* __restrict__ Bhi, const __nv_bfloat16* __restrict__ Blo,
    int KPd,
    const float* __restrict__ bias1, const float* __restrict__ bias2,
    float* __restrict__ out)
{
    __shared__ __align__(16) __nv_bfloat16 sAh[2][128 * TSTR];
    __shared__ __align__(16) __nv_bfloat16 sAl[2][128 * TSTR];
    __shared__ __align__(16) __nv_bfloat16 sBh[2][128 * TSTR];
    __shared__ __align__(16) __nv_bfloat16 sBl[2][128 * TSTR];
    const int tid  = threadIdx.x;
    const int lane = tid & 31;
    const int wid  = tid >> 5;
    const int g    = lane >> 2, tig = lane & 3;
    const int wm   = wid & 1;
    const int wn   = wid >> 1;
    const int n0 = blockIdx.x * 128;
    const int m0 = blockIdx.y * 128;

    const int srow = tid >> 1;
    const int sseg = (tid & 1) * 8;
    const __nv_bfloat16* pAh = Ahi + (size_t)(m0 + srow) * KPd + sseg;
    const __nv_bfloat16* pAl = Alo + (size_t)(m0 + srow) * KPd + sseg;
    const __nv_bfloat16* pBh = Bhi + (size_t)(n0 + srow) * KPd + sseg;
    const __nv_bfloat16* pBl = Blo + (size_t)(n0 + srow) * KPd + sseg;
    const int soff = srow * TSTR + sseg;

    float acc[4][4][4];
#pragma unroll
    for (int mi = 0; mi < 4; mi++)
#pragma unroll
        for (int ni = 0; ni < 4; ni++)
#pragma unroll
            for (int q = 0; q < 4; q++) acc[mi][ni][q] = 0.f;

    const int nch = KPd >> 4;

    *(uint4*)&sAh[0][soff] = *(const uint4*)(pAh);
    *(uint4*)&sAl[0][soff] = *(const uint4*)(pAl);
    *(uint4*)&sBh[0][soff] = *(const uint4*)(pBh);
    *(uint4*)&sBl[0][soff] = *(const uint4*)(pBl);
    __syncthreads();

    for (int kt = 0; kt < nch; kt++) {
        int buf = kt & 1;
        uint4 vah, val, vbh, vbl;
        bool next = (kt + 1 < nch);
        if (next) {
            int ko = (kt + 1) * 16;
            vah = *(const uint4*)(pAh + ko);
            val = *(const uint4*)(pAl + ko);
            vbh = *(const uint4*)(pBh + ko);
            vbl = *(const uint4*)(pBl + ko);
        }
        u32 ah[4][4], al[4][4], bh[4][2], bl[4][2];
        const __nv_bfloat16* Ah = sAh[buf];
        const __nv_bfloat16* Al = sAl[buf];
        const __nv_bfloat16* Bh = sBh[buf];
        const __nv_bfloat16* Bl = sBl[buf];
        const int ca = 2 * tig;
#pragma unroll
        for (int mi = 0; mi < 4; mi++) {
            int r = wm * 64 + mi * 16 + g;
            ah[mi][0] = *(const u32*)&Ah[r * TSTR + ca];
            ah[mi][1] = *(const u32*)&Ah[(r + 8) * TSTR + ca];
            ah[mi][2] = *(const u32*)&Ah[r * TSTR + ca + 8];
            ah[mi][3] = *(const u32*)&Ah[(r + 8) * TSTR + ca + 8];
            al[mi][0] = *(const u32*)&Al[r * TSTR + ca];
            al[mi][1] = *(const u32*)&Al[(r + 8) * TSTR + ca];
            al[mi][2] = *(const u32*)&Al[r * TSTR + ca + 8];
            al[mi][3] = *(const u32*)&Al[(r + 8) * TSTR + ca + 8];
        }
#pragma unroll
        for (int ni = 0; ni < 4; ni++) {
            int r = wn * 32 + ni * 8 + g;
            bh[ni][0] = *(const u32*)&Bh[r * TSTR + ca];
            bh[ni][1] = *(const u32*)&Bh[r * TSTR + ca + 8];
            bl[ni][0] = *(const u32*)&Bl[r * TSTR + ca];
            bl[ni][1] = *(const u32*)&Bl[r * TSTR + ca + 8];
        }
#pragma unroll
        for (int mi = 0; mi < 4; mi++)
#pragma unroll
            for (int ni = 0; ni < 4; ni++) {
                MMA_BF16(acc[mi][ni], ah[mi], bh[ni]);
                MMA_BF16(acc[mi][ni], ah[mi], bl[ni]);
                MMA_BF16(acc[mi][ni], al[mi], bh[ni]);
            }
        if (next) {
            int nb = buf ^ 1;
            *(uint4*)&sAh[nb][soff] = vah;
            *(uint4*)&sAl[nb][soff] = val;
            *(uint4*)&sBh[nb][soff] = vbh;
            *(uint4*)&sBl[nb][soff] = vbl;
            __syncthreads();
        }
    }
#pragma unroll
    for (int ni = 0; ni < 4; ni++) {
        int j0 = n0 + wn * 32 + ni * 8 + 2 * tig;
        float bs0 = bias1[j0] + bias2[j0];
        float bs1 = bias1[j0 + 1] + bias2[j0 + 1];
#pragma unroll
        for (int mi = 0; mi < 4; mi++) {
            int m = m0 + wm * 64 + mi * 16 + g;
            float2 v0 = make_float2(acc[mi][ni][0] + bs0, acc[mi][ni][1] + bs1);
            float2 v1 = make_float2(acc[mi][ni][2] + bs0, acc[mi][ni][3] + bs1);
            *(float2*)(out + (size_t)m * G4H + j0)       = v0;
            *(float2*)(out + (size_t)(m + 8) * G4H + j0) = v1;
        }
    }
}

// ---------------- persistent HMMA LSTM recurrence ----------------------------
// 128 CTAs = 4 batch-blocks(64) x 32 col-blocks(64 gate-cols). Resident W_hh
// bf16 hi/lo in smem (192KB); per step: 3-MMA split GEMM (8 warps, 16x32 warp
// tile), acc -> smem -> gate pass (R3 mapping), h written as bf16 hi/lo (+fp32
// optionally). Global barrier per step.
#define WCH  (64 * TSTR)                 // 1536 bf16 per 16-k chunk
#define W_ELEMS (32 * WCH)               // per dtype
#define HST_ELEMS WCH
#define SM_ACC_OFF (2 * W_ELEMS * 2 + 2 * 2 * HST_ELEMS * 2)  // bytes: W + hstage
#define SMEM_LSTM (SM_ACC_OFF + 64 * 68 * 4)                   // + acc tile

__global__ __launch_bounds__(256, 1) void lstm_mma_kernel(
    const float* __restrict__ gx,          // [S*B, 2048] biases folded
    const __nv_bfloat16* __restrict__ whi, // [2048, 512]
    const __nv_bfloat16* __restrict__ wlo,
    __nv_bfloat16* __restrict__ hhi,       // [S*B, 512]
    __nv_bfloat16* __restrict__ hlo,
    float* __restrict__ hf32)              // nullable
{
    extern __shared__ char smraw[];
    __nv_bfloat16* Wst = (__nv_bfloat16*)smraw;          // [2 dtype][32 chunk][WCH]
    __nv_bfloat16* Hst = Wst + 2 * W_ELEMS;              // [2 buf][2 dtype][WCH]
    float* accS = (float*)(smraw + SM_ACC_OFF);          // [64][68]
    const int tid = threadIdx.x;
    const int bid = blockIdx.x;
    const int m0  = (bid & 3) * 64;
    const int hh0 = (bid >> 2) * 16;
    const int lane = tid & 31, wid = tid >> 5;
    const int g = lane >> 2, tig = lane & 3;
    const int wm = wid & 3, wn = wid >> 2;     // warp tile: rows wm*16, cols wn*32
    const int tx = tid & 15, ty = tid >> 4;    // gate pass mapping (R3)

    // stage resident W: col c -> gate row j = (c&3)*512 + hh0 + (c>>2)
    {
        int c = tid >> 2, q = tid & 3;
        int j = (c & 3) * HHD + hh0 + (c >> 2);
        const __nv_bfloat16* wh = whi + (size_t)j * HHD;
        const __nv_bfloat16* wl = wlo + (size_t)j * HHD;
#pragma unroll 4
        for (int kc = 0; kc < 32; kc++) {
            int k = kc * 16 + q * 4;
            *(uint2*)&Wst[kc * WCH + c * TSTR + q * 4]           = *(const uint2*)(wh + k);
            *(uint2*)&Wst[W_ELEMS + kc * WCH + c * TSTR + q * 4] = *(const uint2*)(wl + k);
        }
    }
    __syncthreads();

    const int hh = hh0 + tx;
    float creg[4] = {0.f, 0.f, 0.f, 0.f};
    // h staging map: 256 thr = 2 dtypes x 64 rows x 2 segs
    const int sd   = tid >> 7;
    const int srow = (tid >> 1) & 63;
    const int sseg = (tid & 1) * 8;

    for (int t = 0; t < SSZ; t++) {
        float gxr[4][4];
        const float* gxt = gx + (size_t)t * BB * G4H;
#pragma unroll
        for (int i = 0; i < 4; i++) {
            const float* p = gxt + (size_t)(m0 + ty * 4 + i) * G4H + hh;
            gxr[i][0] = __ldcg(p);
            gxr[i][1] = __ldcg(p + HHD);
            gxr[i][2] = __ldcg(p + 2 * HHD);
            gxr[i][3] = __ldcg(p + 3 * HHD);
        }

        if (t > 0) {
            const __nv_bfloat16* hbase = (sd ? hlo : hhi) + (size_t)(t - 1) * BB * HHD;
            const __nv_bfloat16* hb = hbase + (size_t)(m0 + srow) * HHD + sseg;
            float acc[4][4];
#pragma unroll
            for (int ni = 0; ni < 4; ni++)
#pragma unroll
                for (int q = 0; q < 4; q++) acc[ni][q] = 0.f;

            *(uint4*)&Hst[sd * HST_ELEMS + srow * TSTR + sseg] = *(const uint4*)hb;
            __syncthreads();
            int buf = 0;
            for (int kc = 0; kc < 32; kc++) {
                uint4 nx;
                bool nxt = (kc + 1 < 32);
                if (nxt) nx = *(const uint4*)(hb + (kc + 1) * 16);
                const __nv_bfloat16* Ah = Hst + buf * 2 * HST_ELEMS;
                const __nv_bfloat16* Al = Ah + HST_ELEMS;
                const __nv_bfloat16* Wh = Wst + kc * WCH;
                const __nv_bfloat16* Wl = Wst + W_ELEMS + kc * WCH;
                const int ca = 2 * tig;
                u32 ah[4], al[4], bh[4][2], bl[4][2];
                int ar = wm * 16 + g;
                ah[0] = *(const u32*)&Ah[ar * TSTR + ca];
                ah[1] = *(const u32*)&Ah[(ar + 8) * TSTR + ca];
                ah[2] = *(const u32*)&Ah[ar * TSTR + ca + 8];
                ah[3] = *(const u32*)&Ah[(ar + 8) * TSTR + ca + 8];
                al[0] = *(const u32*)&Al[ar * TSTR + ca];
                al[1] = *(const u32*)&Al[(ar + 8) * TSTR + ca];
                al[2] = *(const u32*)&Al[ar * TSTR + ca + 8];
                al[3] = *(const u32*)&Al[(ar + 8) * TSTR + ca + 8];
#pragma unroll
                for (int ni = 0; ni < 4; ni++) {
                    int br = wn * 32 + ni * 8 + g;
                    bh[ni][0] = *(const u32*)&Wh[br * TSTR + ca];
                    bh[ni][1] = *(const u32*)&Wh[br * TSTR + ca + 8];
                    bl[ni][0] = *(const u32*)&Wl[br * TSTR + ca];
                    bl[ni][1] = *(const u32*)&Wl[br * TSTR + ca + 8];
                }
#pragma unroll
                for (int ni = 0; ni < 4; ni++) {
                    MMA_BF16(acc[ni], ah, bh[ni]);
                    MMA_BF16(acc[ni], ah, bl[ni]);
                    MMA_BF16(acc[ni], al, bh[ni]);
                }
                if (nxt) {
                    int nb = buf ^ 1;
                    *(uint4*)&Hst[(nb * 2 + sd) * HST_ELEMS + srow * TSTR + sseg] = nx;
                    __syncthreads();
                    buf = nb;
                }
            }
            // acc -> smem (owner remap for gate pass)
#pragma unroll
            for (int ni = 0; ni < 4; ni++) {
                int c0 = wn * 32 + ni * 8 + 2 * tig;
                int r0 = wm * 16 + g;
                accS[r0 * 68 + c0]       = acc[ni][0];
                accS[r0 * 68 + c0 + 1]   = acc[ni][1];
                accS[(r0 + 8) * 68 + c0]     = acc[ni][2];
                accS[(r0 + 8) * 68 + c0 + 1] = acc[ni][3];
            }
            __syncthreads();
        }

        // gate pass (R3 mapping): col c = 4*hh_i + gate
        __nv_bfloat16* whiT = hhi + (size_t)t * BB * HHD;
        __nv_bfloat16* wloT = hlo + (size_t)t * BB * HHD;
        float* hw = hf32 ? hf32 + (size_t)t * BB * HHD : (float*)0;
#pragma unroll
        for (int i = 0; i < 4; i++) {
            float r0 = gxr[i][0], r1 = gxr[i][1], r2 = gxr[i][2], r3 = gxr[i][3];
            if (t > 0) {
                int rr = (ty * 4 + i) * 68 + 4 * tx;
                r0 += accS[rr]; r1 += accS[rr + 1]; r2 += accS[rr + 2]; r3 += accS[rr + 3];
            }
            float ig = 1.f / (1.f + __expf(-r0));
            float fg = 1.f / (1.f + __expf(-r1));
            float gg = tanhf(r2);
            float og = 1.f / (1.f + __expf(-r3));
            float cn = ig * gg + fg * creg[i];
            creg[i] = cn;
            float hv = og * tanhf(cn);
            size_t off = (size_t)(m0 + ty * 4 + i) * HHD + hh;
            __nv_bfloat16 hb16 = __float2bfloat16(hv);
            whiT[off] = hb16;
            wloT[off] = __float2bfloat16(hv - __bfloat162float(hb16));
            if (hw) hw[off] = hv;
        }

        if (t + 1 < SSZ) {
            __syncthreads();
            if (tid == 0) {
                __threadfence();
                atomicAdd(&g_bar, 1u);
                unsigned tgt = (unsigned)(t + 1) * gridDim.x;
                unsigned v;
                do {
                    asm volatile("ld.global.acquire.gpu.u32 %0, [%1];" : "=r"(v) : "l"(&g_bar));
                } while (v < tgt);
            }
            __syncthreads();
        }
    }
}

// ---------------- FC head (R3-proven): 64x64 tile, transpose store ----------
__global__ __launch_bounds__(256) void fc_kernel(
    const float* __restrict__ A,     // g_h2 [32768, 512]
    const float* __restrict__ W,     // fc_w [414, 512]
    const float* __restrict__ bias,  // fc_b [414]
    float* __restrict__ out)         // [256, 2, 207, 128]
{
    __shared__ __align__(16) float As[2][16][68];
    __shared__ __align__(16) float Bs[2][16][68];
    int m0 = blockIdx.y * 64;
    int n0 = blockIdx.x * 64;
    int tid = threadIdx.x;
    int tx = tid & 15, ty = tid >> 4;
    int lm = tid >> 2;
    int lk = (tid & 3) * 4;
    u64 acc[4][2];
#pragma unroll
    for (int i = 0; i < 4; i++) { acc[i][0] = 0ull; acc[i][1] = 0ull; }
    int jb = n0 + lm;
    bool jv = (jb < KIN);

    {
        float4 a4 = *(const float4*)(A + (size_t)(m0 + lm) * HHD + lk);
        As[0][lk + 0][lm] = a4.x; As[0][lk + 1][lm] = a4.y;
        As[0][lk + 2][lm] = a4.z; As[0][lk + 3][lm] = a4.w;
#pragma unroll
        for (int q = 0; q < 4; q++)
            Bs[0][lk + q][lm] = jv ? W[jb * HHD + lk + q] : 0.f;
    }
    __syncthreads();
    int buf = 0;
    for (int kt = 0; kt < 32; kt++) {
        float4 a4n; float bn[4];
        bool next = (kt + 1 < 32);
        if (next) {
            int kb = (kt + 1) * 16;
            a4n = *(const float4*)(A + (size_t)(m0 + lm) * HHD + kb + lk);
#pragma unroll
            for (int q = 0; q < 4; q++)
                bn[q] = jv ? W[jb * HHD + kb + lk + q] : 0.f;
        }
#pragma unroll
        for (int k = 0; k < 16; k++) {
            float4 av = *(const float4*)&As[buf][k][ty * 4];
            float4 bv = *(const float4*)&Bs[buf][k][tx * 4];
            FMA_TILE(av, bv, acc);
        }
        if (next) {
            int nb = buf ^ 1;
            As[nb][lk + 0][lm] = a4n.x; As[nb][lk + 1][lm] = a4n.y;
            As[nb][lk + 2][lm] = a4n.z; As[nb][lk + 3][lm] = a4n.w;
            Bs[nb][lk + 0][lm] = bn[0]; Bs[nb][lk + 1][lm] = bn[1];
            Bs[nb][lk + 2][lm] = bn[2]; Bs[nb][lk + 3][lm] = bn[3];
            __syncthreads();
            buf = nb;
        }
    }
    float accf[4][4];
#pragma unroll
    for (int i = 0; i < 4; i++) {
        float2 p0 = upk2(acc[i][0]);
        float2 p1 = upk2(acc[i][1]);
        accf[i][0] = p0.x; accf[i][1] = p0.y; accf[i][2] = p1.x; accf[i][3] = p1.y;
    }
#pragma unroll
    for (int i = 0; i < 4; i++) {
        int m = m0 + ty * 4 + i;
        int s = m >> 8;
        int b = m & 255;
#pragma unroll
        for (int jj = 0; jj < 4; jj++) {
            int j = n0 + tx * 4 + jj;
            if (j < KIN) {
                int oc = j / 207;
                int n  = j - oc * 207;
                out[(size_t)((b * 2 + oc) * 207 + n) * SSZ + s] = accf[i][jj] + bias[j];
            }
        }
    }
}

// ---------------- launch -----------------------------------------------------
extern "C" void kernel_launch(void* const* d_in, const int* in_sizes, int n_in,
                              void* d_out, int out_size)
{
    const float* x     = (const float*)d_in[0];
    const float* w_ih0 = (const float*)d_in[1];
    const float* w_hh0 = (const float*)d_in[2];
    const float* b_ih0 = (const float*)d_in[3];
    const float* b_hh0 = (const float*)d_in[4];
    const float* w_ih1 = (const float*)d_in[5];
    const float* w_hh1 = (const float*)d_in[6];
    const float* b_ih1 = (const float*)d_in[7];
    const float* b_hh1 = (const float*)d_in[8];
    const float* fc_w  = (const float*)d_in[9];
    const float* fc_b  = (const float*)d_in[10];
    float* out = (float*)d_out;

    float *gx, *h2;
    __nv_bfloat16 *xhi, *xlo, *h1hi, *h1lo, *h2hi, *h2lo;
    __nv_bfloat16 *w0hi, *w0lo, *w1hi, *w1lo, *wh0hi, *wh0lo, *wh1hi, *wh1lo;
    cudaGetSymbolAddress((void**)&gx,   g_gx);
    cudaGetSymbolAddress((void**)&h2,   g_h2);
    cudaGetSymbolAddress((void**)&xhi,  g_xhi);
    cudaGetSymbolAddress((void**)&xlo,  g_xlo);
    cudaGetSymbolAddress((void**)&h1hi, g_h1hi);
    cudaGetSymbolAddress((void**)&h1lo, g_h1lo);
    cudaGetSymbolAddress((void**)&h2hi, g_h2hi);
    cudaGetSymbolAddress((void**)&h2lo, g_h2lo);
    cudaGetSymbolAddress((void**)&w0hi, g_w0hi);
    cudaGetSymbolAddress((void**)&w0lo, g_w0lo);
    cudaGetSymbolAddress((void**)&w1hi, g_w1hi);
    cudaGetSymbolAddress((void**)&w1lo, g_w1lo);
    cudaGetSymbolAddress((void**)&wh0hi, g_wh0hi);
    cudaGetSymbolAddress((void**)&wh0lo, g_wh0lo);
    cudaGetSymbolAddress((void**)&wh1hi, g_wh1hi);
    cudaGetSymbolAddress((void**)&wh1lo, g_wh1lo);

    cudaFuncSetAttribute(lstm_mma_kernel,
                         cudaFuncAttributeMaxDynamicSharedMemorySize, SMEM_LSTM);

    // 1) pack x -> bf16 hi/lo
    pack_x_kernel<<<dim3(256, 14, 4), dim3(32, 8)>>>(x);

    // 2) weight splits (input and recurrent)
    conv_split_kernel<<<(G4H * KP1 + 255) / 256, 256>>>(w_ih0, G4H, KIN, KP1, w0hi, w0lo);
    conv_split_kernel<<<(G4H * KP2 + 255) / 256, 256>>>(w_ih1, G4H, HHD, KP2, w1hi, w1lo);
    conv_split_kernel<<<(G4H * HHD + 255) / 256, 256>>>(w_hh0, G4H, HHD, HHD, wh0hi, wh0lo);
    conv_split_kernel<<<(G4H * HHD + 255) / 256, 256>>>(w_hh1, G4H, HHD, HHD, wh1hi, wh1lo);

    // 3) gx = xs @ w_ih0^T + b_ih0 + b_hh0  (HMMA split-bf16)
    mma_gemm_kernel<<<dim3(G4H / 128, MTOT / 128), 256>>>(
        xhi, xlo, w0hi, w0lo, KP1, b_ih0, b_hh0, gx);

    // 4) layer 1 recurrence (HMMA persistent); writes h1 bf16 hi/lo only
    reset_bar_kernel<<<1, 1>>>();
    lstm_mma_kernel<<<128, 256, SMEM_LSTM>>>(gx, wh0hi, wh0lo, h1hi, h1lo, (float*)0);

    // 5) gx = h1 @ w_ih1^T + b_ih1 + b_hh1  (consumes h1 hi/lo directly)
    mma_gemm_kernel<<<dim3(G4H / 128, MTOT / 128), 256>>>(
        h1hi, h1lo, w1hi, w1lo, KP2, b_ih1, b_hh1, gx);

    // 6) layer 2 recurrence; also writes fp32 h2 for FC
    reset_bar_kernel<<<1, 1>>>();
    lstm_mma_kernel<<<128, 256, SMEM_LSTM>>>(gx, wh1hi, wh1lo, h2hi, h2lo, h2);

    // 7) FC head + output transpose (fp32)
    fc_kernel<<<dim3(7, MTOT / 64), 256>>>(h2, fc_w, fc_b, out);
}

// round 17
// speedup vs baseline: 1.3391x; 1.0699x over previous
#include <cuda_runtime.h>
#include <cuda_bf16.h>
#include <math.h>

#define BB   256      // batch
#define SSZ  128      // seq len
#define HHD  512      // hidden
#define G4H  2048     // 4*H
#define KIN  414      // F*N
#define KP1  448      // layer-1 K padded to 16
#define KP2  512      // layer-2 K
#define MTOT (SSZ*BB) // 32768

typedef unsigned long long u64;
typedef unsigned int u32;

// ---------------- mma.sync bf16 (HMMA fallback; legal on compute_103) --------
#define MMA_BF16(c, a, b) \
    asm volatile("mma.sync.aligned.m16n8k16.row.col.f32.bf16.bf16.f32 " \
        "{%0,%1,%2,%3}, {%4,%5,%6,%7}, {%8,%9}, {%0,%1,%2,%3};" \
        : "+f"((c)[0]), "+f"((c)[1]), "+f"((c)[2]), "+f"((c)[3]) \
        : "r"((a)[0]), "r"((a)[1]), "r"((a)[2]), "r"((a)[3]), \
          "r"((b)[0]), "r"((b)[1]))

// ---------------- scratch (device globals; no allocations allowed) ----------
__device__ __align__(256) float g_gx[MTOT * G4H];    // [S*B, 2048]
__device__ __align__(256) __nv_bfloat16 g_xhi[MTOT * KP1];
__device__ __align__(256) __nv_bfloat16 g_xlo[MTOT * KP1];
__device__ __align__(256) __nv_bfloat16 g_h1hi[MTOT * KP2];
__device__ __align__(256) __nv_bfloat16 g_h1lo[MTOT * KP2];
__device__ __align__(256) __nv_bfloat16 g_h2hi[MTOT * KP2];
__device__ __align__(256) __nv_bfloat16 g_h2lo[MTOT * KP2];
__device__ __align__(256) __nv_bfloat16 g_w0hi[G4H * KP1];
__device__ __align__(256) __nv_bfloat16 g_w0lo[G4H * KP1];
__device__ __align__(256) __nv_bfloat16 g_w1hi[G4H * KP2];
__device__ __align__(256) __nv_bfloat16 g_w1lo[G4H * KP2];
__device__ __align__(256) __nv_bfloat16 g_wh0hi[G4H * HHD];
__device__ __align__(256) __nv_bfloat16 g_wh0lo[G4H * HHD];
__device__ __align__(256) __nv_bfloat16 g_wh1hi[G4H * HHD];
__device__ __align__(256) __nv_bfloat16 g_wh1lo[G4H * HHD];
__device__ __align__(256) __nv_bfloat16 g_fwhi[512 * KP2];   // fc_w padded 512 rows
__device__ __align__(256) __nv_bfloat16 g_fwlo[512 * KP2];
__device__ unsigned int g_bar;

__global__ void reset_bar_kernel() { g_bar = 0u; }

// ---------------- pack x[B,F,N,S] -> bf16 hi/lo [S*B, 448] -------------------
__global__ void pack_x_kernel(const float* __restrict__ x) {
    __shared__ float tile[32][33];
    int b  = blockIdx.x;
    int k0 = blockIdx.y * 32;
    int s0 = blockIdx.z * 32;
    int tx = threadIdx.x, ty = threadIdx.y;  // 32 x 8
    const float* xb = x + (size_t)b * KIN * SSZ;
#pragma unroll
    for (int i = 0; i < 4; i++) {
        int k = k0 + ty + 8 * i;
        if (k < KIN) tile[ty + 8 * i][tx] = xb[k * SSZ + s0 + tx];
    }
    __syncthreads();
#pragma unroll
    for (int i = 0; i < 4; i++) {
        int s = s0 + ty + 8 * i;
        int k = k0 + tx;
        float v = (k < KIN) ? tile[tx][ty + 8 * i] : 0.f;
        __nv_bfloat16 hi = __float2bfloat16(v);
        float lo = v - __bfloat162float(hi);
        size_t o = (size_t)(s * BB + b) * KP1 + k;
        g_xhi[o] = hi;
        g_xlo[o] = __float2bfloat16(lo);
    }
}

// ---------------- fp32 -> bf16 hi/lo with row+K pad ---------------------------
__global__ void conv_split_kernel(const float* __restrict__ src, int rows, int Ksrc,
                                  int rows_pad, int KPd,
                                  __nv_bfloat16* __restrict__ hi, __nv_bfloat16* __restrict__ lo) {
    int idx = blockIdx.x * blockDim.x + threadIdx.x;
    if (idx >= rows_pad * KPd) return;
    int r = idx / KPd, k = idx - r * KPd;
    float v = (r < rows && k < Ksrc) ? src[(size_t)r * Ksrc + k] : 0.f;
    __nv_bfloat16 h = __float2bfloat16(v);
    hi[idx] = h;
    lo[idx] = __float2bfloat16(v - __bfloat162float(h));
}

// ---------------- HMMA split-bf16 GEMM (R12-proven; now 2 CTAs/SM) -----------
#define TSTR 24

__global__ __launch_bounds__(256, 2) void mma_gemm_kernel(
    const __nv_bfloat16* __restrict__ Ahi, const __nv_bfloat16* __restrict__ Alo,
    const __nv_bfloat16* __restrict__ Bhi, const __nv_bfloat16* __restrict__ Blo,
    int KPd,
    const float* __restrict__ bias1, const float* __restrict__ bias2,
    float* __restrict__ out)
{
    __shared__ __align__(16) __nv_bfloat16 sAh[2][128 * TSTR];
    __shared__ __align__(16) __nv_bfloat16 sAl[2][128 * TSTR];
    __shared__ __align__(16) __nv_bfloat16 sBh[2][128 * TSTR];
    __shared__ __align__(16) __nv_bfloat16 sBl[2][128 * TSTR];
    const int tid  = threadIdx.x;
    const int lane = tid & 31;
    const int wid  = tid >> 5;
    const int g    = lane >> 2, tig = lane & 3;
    const int wm   = wid & 1;
    const int wn   = wid >> 1;
    const int n0 = blockIdx.x * 128;
    const int m0 = blockIdx.y * 128;

    const int srow = tid >> 1;
    const int sseg = (tid & 1) * 8;
    const __nv_bfloat16* pAh = Ahi + (size_t)(m0 + srow) * KPd + sseg;
    const __nv_bfloat16* pAl = Alo + (size_t)(m0 + srow) * KPd + sseg;
    const __nv_bfloat16* pBh = Bhi + (size_t)(n0 + srow) * KPd + sseg;
    const __nv_bfloat16* pBl = Blo + (size_t)(n0 + srow) * KPd + sseg;
    const int soff = srow * TSTR + sseg;

    float acc[4][4][4];
#pragma unroll
    for (int mi = 0; mi < 4; mi++)
#pragma unroll
        for (int ni = 0; ni < 4; ni++)
#pragma unroll
            for (int q = 0; q < 4; q++) acc[mi][ni][q] = 0.f;

    const int nch = KPd >> 4;

    *(uint4*)&sAh[0][soff] = *(const uint4*)(pAh);
    *(uint4*)&sAl[0][soff] = *(const uint4*)(pAl);
    *(uint4*)&sBh[0][soff] = *(const uint4*)(pBh);
    *(uint4*)&sBl[0][soff] = *(const uint4*)(pBl);
    __syncthreads();

    for (int kt = 0; kt < nch; kt++) {
        int buf = kt & 1;
        uint4 vah, val, vbh, vbl;
        bool next = (kt + 1 < nch);
        if (next) {
            int ko = (kt + 1) * 16;
            vah = *(const uint4*)(pAh + ko);
            val = *(const uint4*)(pAl + ko);
            vbh = *(const uint4*)(pBh + ko);
            vbl = *(const uint4*)(pBl + ko);
        }
        u32 ah[4][4], al[4][4], bh[4][2], bl[4][2];
        const __nv_bfloat16* Ah = sAh[buf];
        const __nv_bfloat16* Al = sAl[buf];
        const __nv_bfloat16* Bh = sBh[buf];
        const __nv_bfloat16* Bl = sBl[buf];
        const int ca = 2 * tig;
#pragma unroll
        for (int mi = 0; mi < 4; mi++) {
            int r = wm * 64 + mi * 16 + g;
            ah[mi][0] = *(const u32*)&Ah[r * TSTR + ca];
            ah[mi][1] = *(const u32*)&Ah[(r + 8) * TSTR + ca];
            ah[mi][2] = *(const u32*)&Ah[r * TSTR + ca + 8];
            ah[mi][3] = *(const u32*)&Ah[(r + 8) * TSTR + ca + 8];
            al[mi][0] = *(const u32*)&Al[r * TSTR + ca];
            al[mi][1] = *(const u32*)&Al[(r + 8) * TSTR + ca];
            al[mi][2] = *(const u32*)&Al[r * TSTR + ca + 8];
            al[mi][3] = *(const u32*)&Al[(r + 8) * TSTR + ca + 8];
        }
#pragma unroll
        for (int ni = 0; ni < 4; ni++) {
            int r = wn * 32 + ni * 8 + g;
            bh[ni][0] = *(const u32*)&Bh[r * TSTR + ca];
            bh[ni][1] = *(const u32*)&Bh[r * TSTR + ca + 8];
            bl[ni][0] = *(const u32*)&Bl[r * TSTR + ca];
            bl[ni][1] = *(const u32*)&Bl[r * TSTR + ca + 8];
        }
#pragma unroll
        for (int mi = 0; mi < 4; mi++)
#pragma unroll
            for (int ni = 0; ni < 4; ni++) {
                MMA_BF16(acc[mi][ni], ah[mi], bh[ni]);
                MMA_BF16(acc[mi][ni], ah[mi], bl[ni]);
                MMA_BF16(acc[mi][ni], al[mi], bh[ni]);
            }
        if (next) {
            int nb = buf ^ 1;
            *(uint4*)&sAh[nb][soff] = vah;
            *(uint4*)&sAl[nb][soff] = val;
            *(uint4*)&sBh[nb][soff] = vbh;
            *(uint4*)&sBl[nb][soff] = vbl;
            __syncthreads();
        }
    }
#pragma unroll
    for (int ni = 0; ni < 4; ni++) {
        int j0 = n0 + wn * 32 + ni * 8 + 2 * tig;
        float bs0 = bias1[j0] + bias2[j0];
        float bs1 = bias1[j0 + 1] + bias2[j0 + 1];
#pragma unroll
        for (int mi = 0; mi < 4; mi++) {
            int m = m0 + wm * 64 + mi * 16 + g;
            float2 v0 = make_float2(acc[mi][ni][0] + bs0, acc[mi][ni][1] + bs1);
            float2 v1 = make_float2(acc[mi][ni][2] + bs0, acc[mi][ni][3] + bs1);
            *(float2*)(out + (size_t)m * G4H + j0)       = v0;
            *(float2*)(out + (size_t)(m + 8) * G4H + j0) = v1;
        }
    }
}

// ---------------- HMMA FC head: same mainloop, transpose-store epilogue ------
__global__ __launch_bounds__(256, 2) void fc_mma_kernel(
    const __nv_bfloat16* __restrict__ Ahi, const __nv_bfloat16* __restrict__ Alo,
    const __nv_bfloat16* __restrict__ Bhi, const __nv_bfloat16* __restrict__ Blo,
    const float* __restrict__ bias,
    float* __restrict__ out)               // [256, 2, 207, 128]
{
    __shared__ __align__(16) __nv_bfloat16 sAh[2][128 * TSTR];
    __shared__ __align__(16) __nv_bfloat16 sAl[2][128 * TSTR];
    __shared__ __align__(16) __nv_bfloat16 sBh[2][128 * TSTR];
    __shared__ __align__(16) __nv_bfloat16 sBl[2][128 * TSTR];
    const int tid  = threadIdx.x;
    const int lane = tid & 31;
    const int wid  = tid >> 5;
    const int g    = lane >> 2, tig = lane & 3;
    const int wm   = wid & 1;
    const int wn   = wid >> 1;
    const int n0 = blockIdx.x * 128;
    const int m0 = blockIdx.y * 128;
    const int KPd = KP2;

    const int srow = tid >> 1;
    const int sseg = (tid & 1) * 8;
    const __nv_bfloat16* pAh = Ahi + (size_t)(m0 + srow) * KPd + sseg;
    const __nv_bfloat16* pAl = Alo + (size_t)(m0 + srow) * KPd + sseg;
    const __nv_bfloat16* pBh = Bhi + (size_t)(n0 + srow) * KPd + sseg;
    const __nv_bfloat16* pBl = Blo + (size_t)(n0 + srow) * KPd + sseg;
    const int soff = srow * TSTR + sseg;

    float acc[4][4][4];
#pragma unroll
    for (int mi = 0; mi < 4; mi++)
#pragma unroll
        for (int ni = 0; ni < 4; ni++)
#pragma unroll
            for (int q = 0; q < 4; q++) acc[mi][ni][q] = 0.f;

    const int nch = KPd >> 4;

    *(uint4*)&sAh[0][soff] = *(const uint4*)(pAh);
    *(uint4*)&sAl[0][soff] = *(const uint4*)(pAl);
    *(uint4*)&sBh[0][soff] = *(const uint4*)(pBh);
    *(uint4*)&sBl[0][soff] = *(const uint4*)(pBl);
    __syncthreads();

    for (int kt = 0; kt < nch; kt++) {
        int buf = kt & 1;
        uint4 vah, val, vbh, vbl;
        bool next = (kt + 1 < nch);
        if (next) {
            int ko = (kt + 1) * 16;
            vah = *(const uint4*)(pAh + ko);
            val = *(const uint4*)(pAl + ko);
            vbh = *(const uint4*)(pBh + ko);
            vbl = *(const uint4*)(pBl + ko);
        }
        u32 ah[4][4], al[4][4], bh[4][2], bl[4][2];
        const __nv_bfloat16* Ah = sAh[buf];
        const __nv_bfloat16* Al = sAl[buf];
        const __nv_bfloat16* Bh = sBh[buf];
        const __nv_bfloat16* Bl = sBl[buf];
        const int ca = 2 * tig;
#pragma unroll
        for (int mi = 0; mi < 4; mi++) {
            int r = wm * 64 + mi * 16 + g;
            ah[mi][0] = *(const u32*)&Ah[r * TSTR + ca];
            ah[mi][1] = *(const u32*)&Ah[(r + 8) * TSTR + ca];
            ah[mi][2] = *(const u32*)&Ah[r * TSTR + ca + 8];
            ah[mi][3] = *(const u32*)&Ah[(r + 8) * TSTR + ca + 8];
            al[mi][0] = *(const u32*)&Al[r * TSTR + ca];
            al[mi][1] = *(const u32*)&Al[(r + 8) * TSTR + ca];
            al[mi][2] = *(const u32*)&Al[r * TSTR + ca + 8];
            al[mi][3] = *(const u32*)&Al[(r + 8) * TSTR + ca + 8];
        }
#pragma unroll
        for (int ni = 0; ni < 4; ni++) {
            int r = wn * 32 + ni * 8 + g;
            bh[ni][0] = *(const u32*)&Bh[r * TSTR + ca];
            bh[ni][1] = *(const u32*)&Bh[r * TSTR + ca + 8];
            bl[ni][0] = *(const u32*)&Bl[r * TSTR + ca];
            bl[ni][1] = *(const u32*)&Bl[r * TSTR + ca + 8];
        }
#pragma unroll
        for (int mi = 0; mi < 4; mi++)
#pragma unroll
            for (int ni = 0; ni < 4; ni++) {
                MMA_BF16(acc[mi][ni], ah[mi], bh[ni]);
                MMA_BF16(acc[mi][ni], ah[mi], bl[ni]);
                MMA_BF16(acc[mi][ni], al[mi], bh[ni]);
            }
        if (next) {
            int nb = buf ^ 1;
            *(uint4*)&sAh[nb][soff] = vah;
            *(uint4*)&sAl[nb][soff] = val;
            *(uint4*)&sBh[nb][soff] = vbh;
            *(uint4*)&sBl[nb][soff] = vbl;
            __syncthreads();
        }
    }
    // transpose-store epilogue: out[b, oc, n, s], j < 414 guard
#pragma unroll
    for (int ni = 0; ni < 4; ni++) {
        int j0 = n0 + wn * 32 + ni * 8 + 2 * tig;
#pragma unroll
        for (int jj = 0; jj < 2; jj++) {
            int j = j0 + jj;
            if (j >= KIN) continue;
            int oc = j / 207;
            int n  = j - oc * 207;
            float bs = bias[j];
            float* pc = out + (size_t)((/*b*/0 * 2 + oc) * 207 + n) * SSZ;  // base; b added below
#pragma unroll
            for (int mi = 0; mi < 4; mi++) {
                int m = m0 + wm * 64 + mi * 16 + g;
                int s = m >> 8, b = m & 255;
                out[(size_t)((b * 2 + oc) * 207 + n) * SSZ + s] = acc[mi][ni][jj] + bs;
                int m2 = m + 8;
                int s2 = m2 >> 8, b2 = m2 & 255;
                out[(size_t)((b2 * 2 + oc) * 207 + n) * SSZ + s2] = acc[mi][ni][2 + jj] + bs;
            }
            (void)pc;
        }
    }
}

// ---------------- persistent HMMA LSTM recurrence (R14-proven) ---------------
#define WCH  (64 * TSTR)
#define W_ELEMS (32 * WCH)
#define HST_ELEMS WCH
#define SM_ACC_OFF (2 * W_ELEMS * 2 + 2 * 2 * HST_ELEMS * 2)
#define SMEM_LSTM (SM_ACC_OFF + 64 * 68 * 4)

__global__ __launch_bounds__(256, 1) void lstm_mma_kernel(
    const float* __restrict__ gx,
    const __nv_bfloat16* __restrict__ whi,
    const __nv_bfloat16* __restrict__ wlo,
    __nv_bfloat16* __restrict__ hhi,
    __nv_bfloat16* __restrict__ hlo)
{
    extern __shared__ char smraw[];
    __nv_bfloat16* Wst = (__nv_bfloat16*)smraw;
    __nv_bfloat16* Hst = Wst + 2 * W_ELEMS;
    float* accS = (float*)(smraw + SM_ACC_OFF);
    const int tid = threadIdx.x;
    const int bid = blockIdx.x;
    const int m0  = (bid & 3) * 64;
    const int hh0 = (bid >> 2) * 16;
    const int lane = tid & 31, wid = tid >> 5;
    const int g = lane >> 2, tig = lane & 3;
    const int wm = wid & 3, wn = wid >> 2;
    const int tx = tid & 15, ty = tid >> 4;

    {
        int c = tid >> 2, q = tid & 3;
        int j = (c & 3) * HHD + hh0 + (c >> 2);
        const __nv_bfloat16* wh = whi + (size_t)j * HHD;
        const __nv_bfloat16* wl = wlo + (size_t)j * HHD;
#pragma unroll 4
        for (int kc = 0; kc < 32; kc++) {
            int k = kc * 16 + q * 4;
            *(uint2*)&Wst[kc * WCH + c * TSTR + q * 4]           = *(const uint2*)(wh + k);
            *(uint2*)&Wst[W_ELEMS + kc * WCH + c * TSTR + q * 4] = *(const uint2*)(wl + k);
        }
    }
    __syncthreads();

    const int hh = hh0 + tx;
    float creg[4] = {0.f, 0.f, 0.f, 0.f};
    const int sd   = tid >> 7;
    const int srow = (tid >> 1) & 63;
    const int sseg = (tid & 1) * 8;

    for (int t = 0; t < SSZ; t++) {
        float gxr[4][4];
        const float* gxt = gx + (size_t)t * BB * G4H;
#pragma unroll
        for (int i = 0; i < 4; i++) {
            const float* p = gxt + (size_t)(m0 + ty * 4 + i) * G4H + hh;
            gxr[i][0] = __ldcg(p);
            gxr[i][1] = __ldcg(p + HHD);
            gxr[i][2] = __ldcg(p + 2 * HHD);
            gxr[i][3] = __ldcg(p + 3 * HHD);
        }

        if (t > 0) {
            const __nv_bfloat16* hbase = (sd ? hlo : hhi) + (size_t)(t - 1) * BB * HHD;
            const __nv_bfloat16* hb = hbase + (size_t)(m0 + srow) * HHD + sseg;
            float acc[4][4];
#pragma unroll
            for (int ni = 0; ni < 4; ni++)
#pragma unroll
                for (int q = 0; q < 4; q++) acc[ni][q] = 0.f;

            *(uint4*)&Hst[sd * HST_ELEMS + srow * TSTR + sseg] = *(const uint4*)hb;
            __syncthreads();
            int buf = 0;
            for (int kc = 0; kc < 32; kc++) {
                uint4 nx;
                bool nxt = (kc + 1 < 32);
                if (nxt) nx = *(const uint4*)(hb + (kc + 1) * 16);
                const __nv_bfloat16* Ah = Hst + buf * 2 * HST_ELEMS;
                const __nv_bfloat16* Al = Ah + HST_ELEMS;
                const __nv_bfloat16* Wh = Wst + kc * WCH;
                const __nv_bfloat16* Wl = Wst + W_ELEMS + kc * WCH;
                const int ca = 2 * tig;
                u32 ah[4], al[4], bh[4][2], bl[4][2];
                int ar = wm * 16 + g;
                ah[0] = *(const u32*)&Ah[ar * TSTR + ca];
                ah[1] = *(const u32*)&Ah[(ar + 8) * TSTR + ca];
                ah[2] = *(const u32*)&Ah[ar * TSTR + ca + 8];
                ah[3] = *(const u32*)&Ah[(ar + 8) * TSTR + ca + 8];
                al[0] = *(const u32*)&Al[ar * TSTR + ca];
                al[1] = *(const u32*)&Al[(ar + 8) * TSTR + ca];
                al[2] = *(const u32*)&Al[ar * TSTR + ca + 8];
                al[3] = *(const u32*)&Al[(ar + 8) * TSTR + ca + 8];
#pragma unroll
                for (int ni = 0; ni < 4; ni++) {
                    int br = wn * 32 + ni * 8 + g;
                    bh[ni][0] = *(const u32*)&Wh[br * TSTR + ca];
                    bh[ni][1] = *(const u32*)&Wh[br * TSTR + ca + 8];
                    bl[ni][0] = *(const u32*)&Wl[br * TSTR + ca];
                    bl[ni][1] = *(const u32*)&Wl[br * TSTR + ca + 8];
                }
#pragma unroll
                for (int ni = 0; ni < 4; ni++) {
                    MMA_BF16(acc[ni], ah, bh[ni]);
                    MMA_BF16(acc[ni], ah, bl[ni]);
                    MMA_BF16(acc[ni], al, bh[ni]);
                }
                if (nxt) {
                    int nb = buf ^ 1;
                    *(uint4*)&Hst[(nb * 2 + sd) * HST_ELEMS + srow * TSTR + sseg] = nx;
                    __syncthreads();
                    buf = nb;
                }
            }
#pragma unroll
            for (int ni = 0; ni < 4; ni++) {
                int c0 = wn * 32 + ni * 8 + 2 * tig;
                int r0 = wm * 16 + g;
                accS[r0 * 68 + c0]       = acc[ni][0];
                accS[r0 * 68 + c0 + 1]   = acc[ni][1];
                accS[(r0 + 8) * 68 + c0]     = acc[ni][2];
                accS[(r0 + 8) * 68 + c0 + 1] = acc[ni][3];
            }
            __syncthreads();
        }

        __nv_bfloat16* whiT = hhi + (size_t)t * BB * HHD;
        __nv_bfloat16* wloT = hlo + (size_t)t * BB * HHD;
#pragma unroll
        for (int i = 0; i < 4; i++) {
            float r0 = gxr[i][0], r1 = gxr[i][1], r2 = gxr[i][2], r3 = gxr[i][3];
            if (t > 0) {
                int rr = (ty * 4 + i) * 68 + 4 * tx;
                r0 += accS[rr]; r1 += accS[rr + 1]; r2 += accS[rr + 2]; r3 += accS[rr + 3];
            }
            float ig = 1.f / (1.f + __expf(-r0));
            float fg = 1.f / (1.f + __expf(-r1));
            float gg = tanhf(r2);
            float og = 1.f / (1.f + __expf(-r3));
            float cn = ig * gg + fg * creg[i];
            creg[i] = cn;
            float hv = og * tanhf(cn);
            size_t off = (size_t)(m0 + ty * 4 + i) * HHD + hh;
            __nv_bfloat16 hb16 = __float2bfloat16(hv);
            whiT[off] = hb16;
            wloT[off] = __float2bfloat16(hv - __bfloat162float(hb16));
        }

        if (t + 1 < SSZ) {
            __syncthreads();
            if (tid == 0) {
                __threadfence();
                atomicAdd(&g_bar, 1u);
                unsigned tgt = (unsigned)(t + 1) * gridDim.x;
                unsigned v;
                do {
                    asm volatile("ld.global.acquire.gpu.u32 %0, [%1];" : "=r"(v) : "l"(&g_bar));
                } while (v < tgt);
            }
            __syncthreads();
        }
    }
}

// ---------------- launch -----------------------------------------------------
extern "C" void kernel_launch(void* const* d_in, const int* in_sizes, int n_in,
                              void* d_out, int out_size)
{
    const float* x     = (const float*)d_in[0];
    const float* w_ih0 = (const float*)d_in[1];
    const float* w_hh0 = (const float*)d_in[2];
    const float* b_ih0 = (const float*)d_in[3];
    const float* b_hh0 = (const float*)d_in[4];
    const float* w_ih1 = (const float*)d_in[5];
    const float* w_hh1 = (const float*)d_in[6];
    const float* b_ih1 = (const float*)d_in[7];
    const float* b_hh1 = (const float*)d_in[8];
    const float* fc_w  = (const float*)d_in[9];
    const float* fc_b  = (const float*)d_in[10];
    float* out = (float*)d_out;

    float *gx;
    __nv_bfloat16 *xhi, *xlo, *h1hi, *h1lo, *h2hi, *h2lo;
    __nv_bfloat16 *w0hi, *w0lo, *w1hi, *w1lo, *wh0hi, *wh0lo, *wh1hi, *wh1lo, *fwhi, *fwlo;
    cudaGetSymbolAddress((void**)&gx,   g_gx);
    cudaGetSymbolAddress((void**)&xhi,  g_xhi);
    cudaGetSymbolAddress((void**)&xlo,  g_xlo);
    cudaGetSymbolAddress((void**)&h1hi, g_h1hi);
    cudaGetSymbolAddress((void**)&h1lo, g_h1lo);
    cudaGetSymbolAddress((void**)&h2hi, g_h2hi);
    cudaGetSymbolAddress((void**)&h2lo, g_h2lo);
    cudaGetSymbolAddress((void**)&w0hi, g_w0hi);
    cudaGetSymbolAddress((void**)&w0lo, g_w0lo);
    cudaGetSymbolAddress((void**)&w1hi, g_w1hi);
    cudaGetSymbolAddress((void**)&w1lo, g_w1lo);
    cudaGetSymbolAddress((void**)&wh0hi, g_wh0hi);
    cudaGetSymbolAddress((void**)&wh0lo, g_wh0lo);
    cudaGetSymbolAddress((void**)&wh1hi, g_wh1hi);
    cudaGetSymbolAddress((void**)&wh1lo, g_wh1lo);
    cudaGetSymbolAddress((void**)&fwhi, g_fwhi);
    cudaGetSymbolAddress((void**)&fwlo, g_fwlo);

    cudaFuncSetAttribute(lstm_mma_kernel,
                         cudaFuncAttributeMaxDynamicSharedMemorySize, SMEM_LSTM);

    // 1) pack x -> bf16 hi/lo
    pack_x_kernel<<<dim3(256, 14, 4), dim3(32, 8)>>>(x);

    // 2) weight splits (input, recurrent, fc)
    conv_split_kernel<<<(G4H * KP1 + 255) / 256, 256>>>(w_ih0, G4H, KIN, G4H, KP1, w0hi, w0lo);
    conv_split_kernel<<<(G4H * KP2 + 255) / 256, 256>>>(w_ih1, G4H, HHD, G4H, KP2, w1hi, w1lo);
    conv_split_kernel<<<(G4H * HHD + 255) / 256, 256>>>(w_hh0, G4H, HHD, G4H, HHD, wh0hi, wh0lo);
    conv_split_kernel<<<(G4H * HHD + 255) / 256, 256>>>(w_hh1, G4H, HHD, G4H, HHD, wh1hi, wh1lo);
    conv_split_kernel<<<(512 * KP2 + 255) / 256, 256>>>(fc_w, KIN, HHD, 512, KP2, fwhi, fwlo);

    // 3) gx = xs @ w_ih0^T + b_ih0 + b_hh0  (HMMA split-bf16)
    mma_gemm_kernel<<<dim3(G4H / 128, MTOT / 128), 256>>>(
        xhi, xlo, w0hi, w0lo, KP1, b_ih0, b_hh0, gx);

    // 4) layer 1 recurrence (HMMA persistent)
    reset_bar_kernel<<<1, 1>>>();
    lstm_mma_kernel<<<128, 256, SMEM_LSTM>>>(gx, wh0hi, wh0lo, h1hi, h1lo);

    // 5) gx = h1 @ w_ih1^T + b_ih1 + b_hh1
    mma_gemm_kernel<<<dim3(G4H / 128, MTOT / 128), 256>>>(
        h1hi, h1lo, w1hi, w1lo, KP2, b_ih1, b_hh1, gx);

    // 6) layer 2 recurrence
    reset_bar_kernel<<<1, 1>>>();
    lstm_mma_kernel<<<128, 256, SMEM_LSTM>>>(gx, wh1hi, wh1lo, h2hi, h2lo);

    // 7) FC head (HMMA) + output transpose
    fc_mma_kernel<<<dim3(4, MTOT / 128), 256>>>(h2hi, h2lo, fwhi, fwlo, fc_b, out);
}